// round 11
// baseline (speedup 1.0000x reference)
#include <cuda_runtime.h>
#include <cuda_fp16.h>
#include <cstdint>
#include <math.h>

#define B_   2
#define S_   2048
#define D_   1024
#define H_   16
#define DK_  64
#define NROWS (B_ * S_)   // 4096
#define NWORDS (S_ / 64)  // 32 u64 mask words per row

// Scratch (allocation-free rule: __device__ globals). All fp16.
__device__ __half g_Q[NROWS * D_];            // Q proj, pre-scaled by 0.125
__device__ __half g_K[NROWS * D_];            // K proj
__device__ __half g_Vt[(size_t)D_ * NROWS];   // V proj TRANSPOSED: [dim][b*S+tok]
__device__ __half g_A[NROWS * D_];            // attention out
__device__ __half g_qc[NROWS * D_];           // converted activations
__device__ __half g_kc[NROWS * D_];
__device__ __half g_vc[NROWS * D_];
__device__ __half g_wq[D_ * D_];              // converted weights
__device__ __half g_wk[D_ * D_];
__device__ __half g_wv[D_ * D_];
__device__ __half g_wo[D_ * D_];
__device__ unsigned long long g_mbits[(size_t)B_ * S_ * NWORDS];

// ---------------------------------------------------------------------------
// helpers
// ---------------------------------------------------------------------------
__device__ __forceinline__ void mma_f16(float* c, const uint32_t* a,
                                        uint32_t b0, uint32_t b1) {
    asm volatile(
        "mma.sync.aligned.m16n8k16.row.col.f32.f16.f16.f32 "
        "{%0,%1,%2,%3}, {%4,%5,%6,%7}, {%8,%9}, {%0,%1,%2,%3};\n"
        : "+f"(c[0]), "+f"(c[1]), "+f"(c[2]), "+f"(c[3])
        : "r"(a[0]), "r"(a[1]), "r"(a[2]), "r"(a[3]), "r"(b0), "r"(b1));
}

// ldmatrix x4 (b16): four 8x8 fp16 matrices
__device__ __forceinline__ void ldsm4(uint32_t* r, uint32_t saddr) {
    asm volatile(
        "ldmatrix.sync.aligned.m8n8.x4.shared.b16 {%0,%1,%2,%3}, [%4];\n"
        : "=r"(r[0]), "=r"(r[1]), "=r"(r[2]), "=r"(r[3]) : "r"(saddr));
}

__device__ __forceinline__ void cp16(void* sdst, const void* gsrc) {
    uint32_t s = (uint32_t)__cvta_generic_to_shared(sdst);
    asm volatile("cp.async.ca.shared.global [%0], [%1], 16;\n" :: "r"(s), "l"(gsrc));
}
__device__ __forceinline__ uint32_t ld32(const __half* p) {
    return *(const uint32_t*)(const void*)p;
}
__device__ __forceinline__ void st32(__half* p, float lo, float hi) {
    __half2 h = __floats2half2_rn(lo, hi);
    *(__half2*)(void*)p = h;
}

// ---------------------------------------------------------------------------
// fp32 -> fp16 (RN) pre-pass: 8 elements per thread
// ---------------------------------------------------------------------------
__global__ void __launch_bounds__(256) cvt_f16(
    const float* __restrict__ src, __half* __restrict__ dst, int n8)
{
    int i = blockIdx.x * blockDim.x + threadIdx.x;
    if (i >= n8) return;
    const float4* s = (const float4*)src;
    float4 a = s[2 * i], b = s[2 * i + 1];
    union { __half2 h[4]; uint4 u; } o;
    o.h[0] = __floats2half2_rn(a.x, a.y);
    o.h[1] = __floats2half2_rn(a.z, a.w);
    o.h[2] = __floats2half2_rn(b.x, b.y);
    o.h[3] = __floats2half2_rn(b.z, b.w);
    ((uint4*)dst)[i] = o.u;
}

// ---------------------------------------------------------------------------
// mask [B,1,S,S] int32 -> bit-packed u64
// ---------------------------------------------------------------------------
__global__ void __launch_bounds__(256) pack_mask(
    const int* __restrict__ mask, unsigned long long* __restrict__ bits)
{
    int gw = (int)((blockIdx.x * blockDim.x + threadIdx.x) >> 5);
    int lane = threadIdx.x & 31;
    const int* src = mask + (size_t)gw * 64;
    unsigned lo = __ballot_sync(0xffffffffu, src[lane] != 0);
    unsigned hi = __ballot_sync(0xffffffffu, src[lane + 32] != 0);
    bits[gw] = ((unsigned long long)hi << 32) | lo;
}

// ---------------------------------------------------------------------------
// C[M, Nd] = A[M, K] @ W[Nd, K]^T + bias — fp16 mma (m16n8k16), 2-stage
// cp.async. Block 128(m) x 256(n), BK=32, 256 threads; warps 2x4, warp 64x64.
// UNCHANGED from round 10 (proven).
// MODE: 0 = fp32 out (col bias)     1 = fp16 out (col bias)
//       2 = fp16 out * 0.125        3 = fp16 out, bias indexed by ROW
// ---------------------------------------------------------------------------
#define PH 40   // smem pitch in halves (80 B)
template <int MODE>
__global__ void __launch_bounds__(256) gemm_f16(
    const __half* __restrict__ A, const __half* __restrict__ W,
    const float* __restrict__ bias, void* __restrict__ Cv,
    int M, int Nd, int K)
{
    extern __shared__ __half smh[];
    __half* As = smh;                 // 2 * 128 * 40
    __half* Bs = smh + 2 * 128 * PH;  // 2 * 256 * 40

    const int tid  = threadIdx.x;
    const int lane = tid & 31, wid = tid >> 5;
    const int g = lane >> 2, t = lane & 3;
    const int wm = (wid >> 2) * 64;
    const int wn = (wid & 3) * 64;
    const int m0 = blockIdx.y * 128, n0 = blockIdx.x * 256;

    float acc[4][8][4];
    #pragma unroll
    for (int i = 0; i < 4; i++)
        #pragma unroll
        for (int j = 0; j < 8; j++)
            #pragma unroll
            for (int q = 0; q < 4; q++) acc[i][j][q] = 0.f;

    // prologue: stage 0
    {
        #pragma unroll
        for (int j = 0; j < 2; j++) {
            int idx = tid + 256 * j, r = idx >> 2, ch = (idx & 3) * 8;
            cp16(As + r * PH + ch, A + (size_t)(m0 + r) * K + ch);
        }
        #pragma unroll
        for (int j = 0; j < 4; j++) {
            int idx = tid + 256 * j, r = idx >> 2, ch = (idx & 3) * 8;
            cp16(Bs + r * PH + ch, W + (size_t)(n0 + r) * K + ch);
        }
        asm volatile("cp.async.commit_group;\n");
    }

    const int NS = K / 32;
    for (int s = 0; s < NS; s++) {
        asm volatile("cp.async.wait_group 0;\n");
        __syncthreads();
        if (s + 1 < NS) {
            int kt = (s + 1) * 32;
            __half* Ad = As + ((s + 1) & 1) * 128 * PH;
            __half* Bd = Bs + ((s + 1) & 1) * 256 * PH;
            #pragma unroll
            for (int j = 0; j < 2; j++) {
                int idx = tid + 256 * j, r = idx >> 2, ch = (idx & 3) * 8;
                cp16(Ad + r * PH + ch, A + (size_t)(m0 + r) * K + kt + ch);
            }
            #pragma unroll
            for (int j = 0; j < 4; j++) {
                int idx = tid + 256 * j, r = idx >> 2, ch = (idx & 3) * 8;
                cp16(Bd + r * PH + ch, W + (size_t)(n0 + r) * K + kt + ch);
            }
            asm volatile("cp.async.commit_group;\n");
        }
        const __half* Ab = As + (s & 1) * 128 * PH;
        const __half* Bb = Bs + (s & 1) * 256 * PH;

        #pragma unroll
        for (int ks = 0; ks < 2; ks++) {
            uint32_t af[4][4], bf[8][2];
            #pragma unroll
            for (int mt = 0; mt < 4; mt++) {
                int r = wm + mt * 16;
                af[mt][0] = ld32(Ab + (r + g)     * PH + ks * 16 + 2 * t);
                af[mt][1] = ld32(Ab + (r + g + 8) * PH + ks * 16 + 2 * t);
                af[mt][2] = ld32(Ab + (r + g)     * PH + ks * 16 + 2 * t + 8);
                af[mt][3] = ld32(Ab + (r + g + 8) * PH + ks * 16 + 2 * t + 8);
            }
            #pragma unroll
            for (int nt = 0; nt < 8; nt++) {
                int c = wn + nt * 8;
                bf[nt][0] = ld32(Bb + (c + g) * PH + ks * 16 + 2 * t);
                bf[nt][1] = ld32(Bb + (c + g) * PH + ks * 16 + 2 * t + 8);
            }
            #pragma unroll
            for (int mt = 0; mt < 4; mt++)
                #pragma unroll
                for (int nt = 0; nt < 8; nt++)
                    mma_f16(acc[mt][nt], af[mt], bf[nt][0], bf[nt][1]);
        }
    }

    // epilogue
    #pragma unroll
    for (int mt = 0; mt < 4; mt++) {
        int r0 = m0 + wm + mt * 16 + g;
        float br0 = 0.f, br8 = 0.f;
        if (MODE == 3) { br0 = bias[r0]; br8 = bias[r0 + 8]; }
        #pragma unroll
        for (int nt = 0; nt < 8; nt++) {
            int c = n0 + wn + nt * 8 + 2 * t;
            if (MODE == 0) {
                float* C = (float*)Cv;
                float2 bv = *(const float2*)(bias + c);
                *(float2*)(C + (size_t)r0 * Nd + c) =
                    make_float2(acc[mt][nt][0] + bv.x, acc[mt][nt][1] + bv.y);
                *(float2*)(C + (size_t)(r0 + 8) * Nd + c) =
                    make_float2(acc[mt][nt][2] + bv.x, acc[mt][nt][3] + bv.y);
            } else if (MODE == 1) {
                __half* C = (__half*)Cv;
                float2 bv = *(const float2*)(bias + c);
                st32(C + (size_t)r0 * Nd + c,
                     acc[mt][nt][0] + bv.x, acc[mt][nt][1] + bv.y);
                st32(C + (size_t)(r0 + 8) * Nd + c,
                     acc[mt][nt][2] + bv.x, acc[mt][nt][3] + bv.y);
            } else if (MODE == 2) {
                __half* C = (__half*)Cv;
                float2 bv = *(const float2*)(bias + c);
                st32(C + (size_t)r0 * Nd + c,
                     0.125f * (acc[mt][nt][0] + bv.x), 0.125f * (acc[mt][nt][1] + bv.y));
                st32(C + (size_t)(r0 + 8) * Nd + c,
                     0.125f * (acc[mt][nt][2] + bv.x), 0.125f * (acc[mt][nt][3] + bv.y));
            } else {
                __half* C = (__half*)Cv;
                st32(C + (size_t)r0 * Nd + c,
                     acc[mt][nt][0] + br0, acc[mt][nt][1] + br0);
                st32(C + (size_t)(r0 + 8) * Nd + c,
                     acc[mt][nt][2] + br8, acc[mt][nt][3] + br8);
            }
        }
    }
}

// ---------------------------------------------------------------------------
// Flash attention, fp16 mma + LDMATRIX fragment loads. Br=256, 512 threads =
// 16 warps, 16 q-rows each. K [tok][dim]; V [dim][tok] from g_Vt; 2-stage
// cp.async ring. Q pre-scaled by 0.125. Mask bit-packed.
// Per warp per tile: 16+16+4 LDSM replace 144 scalar LDS.
// ---------------------------------------------------------------------------
#define APH 72            // smem pitch in halves (144 B): rows -> distinct 16B groups
#define APB (APH * 2)     // pitch in bytes
__global__ void __launch_bounds__(512, 1) attn_f16(
    const __half* __restrict__ Qg, const __half* __restrict__ Kg,
    const __half* __restrict__ Vtg, const unsigned long long* __restrict__ mbits,
    __half* __restrict__ O)
{
    extern __shared__ __half smh[];
    __half* Qs = smh;                       // 256*72
    __half* Ps = Qs + 256 * APH;            // 256*72
    __half* Ks = Ps + 256 * APH;            // 2 * 64*72
    __half* Vs = Ks + 2 * 64 * APH;         // 2 * 64*72

    const int tid = threadIdx.x;
    const int lane = tid & 31, wid = tid >> 5;
    const int g = lane >> 2, t4 = lane & 3;
    const int w16 = wid * 16;
    const int bh = blockIdx.y, b = bh >> 4, h = bh & 15;
    const int q0 = blockIdx.x * 256;
    const int T = S_ / 64;                  // 32 KV tiles

    // LDSM per-lane address pieces (byte offsets)
    const int rowA = lane & 15;                         // A-pattern rows
    const int offA = (lane & 16) ? 16 : 0;              // +16B for k8 block
    const int rowB = (lane & 7) + ((lane & 16) ? 8 : 0); // B-pattern rows (2 n-blocks)
    const int offB = (lane & 8) ? 16 : 0;
    const uint32_t Qs_u = (uint32_t)__cvta_generic_to_shared(Qs);
    const uint32_t Ps_u = (uint32_t)__cvta_generic_to_shared(Ps);
    const uint32_t Ks_u = (uint32_t)__cvta_generic_to_shared(Ks);
    const uint32_t Vs_u = (uint32_t)__cvta_generic_to_shared(Vs);
    const uint32_t aA = (uint32_t)((w16 + rowA) * APB + offA);  // + ks*32
    const uint32_t aB = (uint32_t)(rowB * APB + offB);          // + nt2*16*APB + ks*32

    const __half* Kg0  = Kg  + ((size_t)(b * S_)) * D_ + h * DK_;
    const __half* Vtg0 = Vtg + (size_t)(h * DK_) * NROWS + b * S_;

    // prologue: stage KV tiles 0 and 1
    #pragma unroll
    for (int pt = 0; pt < 2; pt++) {
        int r = tid >> 3, ch = (tid & 7) * 8;
        cp16(Ks + pt * 64 * APH + r * APH + ch,
             Kg0 + (size_t)(pt * 64 + r) * D_ + ch);
        cp16(Vs + pt * 64 * APH + r * APH + ch,
             Vtg0 + (size_t)r * NROWS + pt * 64 + ch);
        asm volatile("cp.async.commit_group;\n");
    }
    // Q tile [256 x 64]
    {
        const __half* Qb = Qg + ((size_t)(b * S_ + q0)) * D_ + h * DK_;
        #pragma unroll
        for (int j = 0; j < 4; j++) {
            int idx = tid + 512 * j, r = idx >> 3, ch = (idx & 7) * 8;
            cp16(Qs + r * APH + ch, Qb + (size_t)r * D_ + ch);
        }
        asm volatile("cp.async.commit_group;\n");
    }
    asm volatile("cp.async.wait_group 0;\n");
    __syncthreads();

    // Q fragments via LDSM (4 k16-steps)
    uint32_t qf[4][4];
    #pragma unroll
    for (int ks = 0; ks < 4; ks++)
        ldsm4(qf[ks], Qs_u + aA + ks * 32);

    float oacc[8][4];
    #pragma unroll
    for (int i = 0; i < 8; i++)
        #pragma unroll
        for (int j = 0; j < 4; j++) oacc[i][j] = 0.f;
    float mr0 = -INFINITY, mr1 = -INFINITY, lr0 = 0.f, lr1 = 0.f;

    const unsigned long long* mrow0 =
        mbits + (size_t)(b * S_ + q0 + w16 + g) * NWORDS;
    const unsigned long long* mrow1 =
        mbits + (size_t)(b * S_ + q0 + w16 + g + 8) * NWORDS;

    for (int t = 0; t < T; t++) {
        int s = t & 1;
        unsigned long long mw0 = __ldg(mrow0 + t);
        unsigned long long mw1 = __ldg(mrow1 + t);

        if (t > 0) asm volatile("cp.async.wait_group 1;\n");
        __syncthreads();
        const uint32_t Kb_u = Ks_u + s * 64 * APB;
        const uint32_t Vb_u = Vs_u + s * 64 * APB;

        // S = Q K^T (Q pre-scaled); K b-frags via LDSM (2 nt per x4)
        float sacc[8][4];
        #pragma unroll
        for (int i = 0; i < 8; i++)
            #pragma unroll
            for (int j = 0; j < 4; j++) sacc[i][j] = 0.f;
        #pragma unroll
        for (int nt2 = 0; nt2 < 4; nt2++) {
            #pragma unroll
            for (int ks = 0; ks < 4; ks++) {
                uint32_t bq[4];
                ldsm4(bq, Kb_u + aB + nt2 * 16 * APB + ks * 32);
                mma_f16(sacc[2 * nt2],     qf[ks], bq[0], bq[1]);
                mma_f16(sacc[2 * nt2 + 1], qf[ks], bq[2], bq[3]);
            }
        }

        // mask (bit test) + online softmax
        float rm0 = -INFINITY, rm1 = -INFINITY;
        #pragma unroll
        for (int nt = 0; nt < 8; nt++) {
            int sh = nt * 8 + 2 * t4;
            sacc[nt][0] = ((mw0 >> sh) & 1ull)       ? sacc[nt][0] : -1e9f;
            sacc[nt][1] = ((mw0 >> (sh + 1)) & 1ull) ? sacc[nt][1] : -1e9f;
            sacc[nt][2] = ((mw1 >> sh) & 1ull)       ? sacc[nt][2] : -1e9f;
            sacc[nt][3] = ((mw1 >> (sh + 1)) & 1ull) ? sacc[nt][3] : -1e9f;
            rm0 = fmaxf(rm0, fmaxf(sacc[nt][0], sacc[nt][1]));
            rm1 = fmaxf(rm1, fmaxf(sacc[nt][2], sacc[nt][3]));
        }
        rm0 = fmaxf(rm0, __shfl_xor_sync(0xffffffffu, rm0, 1));
        rm0 = fmaxf(rm0, __shfl_xor_sync(0xffffffffu, rm0, 2));
        rm1 = fmaxf(rm1, __shfl_xor_sync(0xffffffffu, rm1, 1));
        rm1 = fmaxf(rm1, __shfl_xor_sync(0xffffffffu, rm1, 2));

        float mn0 = fmaxf(mr0, rm0), mn1 = fmaxf(mr1, rm1);
        float a0 = __expf(mr0 - mn0), a1 = __expf(mr1 - mn1);
        float rs0 = 0.f, rs1 = 0.f;
        #pragma unroll
        for (int nt = 0; nt < 8; nt++) {
            float p0 = __expf(sacc[nt][0] - mn0);
            float p1 = __expf(sacc[nt][1] - mn0);
            float p2 = __expf(sacc[nt][2] - mn1);
            float p3 = __expf(sacc[nt][3] - mn1);
            rs0 += p0 + p1; rs1 += p2 + p3;
            int c = nt * 8 + 2 * t4;
            st32(Ps + (w16 + g)     * APH + c, p0, p1);
            st32(Ps + (w16 + g + 8) * APH + c, p2, p3);
        }
        rs0 += __shfl_xor_sync(0xffffffffu, rs0, 1);
        rs0 += __shfl_xor_sync(0xffffffffu, rs0, 2);
        rs1 += __shfl_xor_sync(0xffffffffu, rs1, 1);
        rs1 += __shfl_xor_sync(0xffffffffu, rs1, 2);
        lr0 = lr0 * a0 + rs0; lr1 = lr1 * a1 + rs1;
        mr0 = mn0; mr1 = mn1;
        #pragma unroll
        for (int nt = 0; nt < 8; nt++) {
            oacc[nt][0] *= a0; oacc[nt][1] *= a0;
            oacc[nt][2] *= a1; oacc[nt][3] *= a1;
        }
        __syncwarp();   // P stores visible to this warp's LDSM reads

        // O += P @ V   (P a-frags via LDSM; V [dim][tok] b-frags via LDSM)
        #pragma unroll
        for (int ks = 0; ks < 4; ks++) {
            uint32_t pa[4];
            ldsm4(pa, Ps_u + aA + ks * 32);
            #pragma unroll
            for (int nt2 = 0; nt2 < 4; nt2++) {
                uint32_t vb[4];
                ldsm4(vb, Vb_u + aB + nt2 * 16 * APB + ks * 32);
                mma_f16(oacc[2 * nt2],     pa, vb[0], vb[1]);
                mma_f16(oacc[2 * nt2 + 1], pa, vb[2], vb[3]);
            }
        }

        __syncthreads();              // all warps done reading stage s
        if (t + 2 < T) {              // refill stage s with tile t+2
            int r = tid >> 3, ch = (tid & 7) * 8;
            cp16(Ks + s * 64 * APH + r * APH + ch,
                 Kg0 + (size_t)((t + 2) * 64 + r) * D_ + ch);
            cp16(Vs + s * 64 * APH + r * APH + ch,
                 Vtg0 + (size_t)r * NROWS + (t + 2) * 64 + ch);
        }
        asm volatile("cp.async.commit_group;\n");   // real or empty: uniform accounting
    }

    // write normalized output (fp16, consumed by final GEMM)
    float i0 = 1.f / lr0, i1 = 1.f / lr1;
    #pragma unroll
    for (int nt = 0; nt < 8; nt++) {
        int c = h * DK_ + nt * 8 + 2 * t4;
        size_t r0 = (size_t)(b * S_ + q0 + w16 + g) * D_ + c;
        size_t r1 = (size_t)(b * S_ + q0 + w16 + g + 8) * D_ + c;
        st32(O + r0, oacc[nt][0] * i0, oacc[nt][1] * i0);
        st32(O + r1, oacc[nt][2] * i1, oacc[nt][3] * i1);
    }
}

// ---------------------------------------------------------------------------
extern "C" void kernel_launch(void* const* d_in, const int* in_sizes, int n_in,
                              void* d_out, int out_size)
{
    const float* q    = (const float*)d_in[0];
    const float* k    = (const float*)d_in[1];
    const float* v    = (const float*)d_in[2];
    const int*   mask = (const int*)  d_in[3];
    const float* w_q  = (const float*)d_in[4];
    const float* b_q  = (const float*)d_in[5];
    const float* w_k  = (const float*)d_in[6];
    const float* b_k  = (const float*)d_in[7];
    const float* w_v  = (const float*)d_in[8];
    const float* b_v  = (const float*)d_in[9];
    const float* w_o  = (const float*)d_in[10];
    const float* b_o  = (const float*)d_in[11];
    float* out = (float*)d_out;

    __half *Qp, *Kp, *Vtp, *Ap, *qc, *kc, *vc, *wq, *wk, *wv, *wo;
    unsigned long long* Mp;
    cudaGetSymbolAddress((void**)&Qp, g_Q);
    cudaGetSymbolAddress((void**)&Kp, g_K);
    cudaGetSymbolAddress((void**)&Vtp, g_Vt);
    cudaGetSymbolAddress((void**)&Ap, g_A);
    cudaGetSymbolAddress((void**)&qc, g_qc);
    cudaGetSymbolAddress((void**)&kc, g_kc);
    cudaGetSymbolAddress((void**)&vc, g_vc);
    cudaGetSymbolAddress((void**)&wq, g_wq);
    cudaGetSymbolAddress((void**)&wk, g_wk);
    cudaGetSymbolAddress((void**)&wv, g_wv);
    cudaGetSymbolAddress((void**)&wo, g_wo);
    cudaGetSymbolAddress((void**)&Mp, g_mbits);

    const int gemm_smem = 2 * (128 + 256) * PH * (int)sizeof(__half);   // 61440
    const int attn_smem = (2 * 256 * APH + 4 * 64 * APH) * (int)sizeof(__half); // 110592

    static bool attr_done = false;
    if (!attr_done) {
        cudaFuncSetAttribute(gemm_f16<0>,
            cudaFuncAttributeMaxDynamicSharedMemorySize, gemm_smem);
        cudaFuncSetAttribute(gemm_f16<1>,
            cudaFuncAttributeMaxDynamicSharedMemorySize, gemm_smem);
        cudaFuncSetAttribute(gemm_f16<2>,
            cudaFuncAttributeMaxDynamicSharedMemorySize, gemm_smem);
        cudaFuncSetAttribute(gemm_f16<3>,
            cudaFuncAttributeMaxDynamicSharedMemorySize, gemm_smem);
        cudaFuncSetAttribute(attn_f16,
            cudaFuncAttributeMaxDynamicSharedMemorySize, attn_smem);
        attr_done = true;
    }

    // pre-passes
    pack_mask<<<(B_ * S_ * NWORDS) / 8, 256>>>(mask, Mp);
    const int nact8 = NROWS * D_ / 8;
    const int nw8   = D_ * D_ / 8;
    cvt_f16<<<nact8 / 256, 256>>>(q, qc, nact8);
    cvt_f16<<<nact8 / 256, 256>>>(k, kc, nact8);
    cvt_f16<<<nact8 / 256, 256>>>(v, vc, nact8);
    cvt_f16<<<nw8 / 256, 256>>>(w_q, wq, nw8);
    cvt_f16<<<nw8 / 256, 256>>>(w_k, wk, nw8);
    cvt_f16<<<nw8 / 256, 256>>>(w_v, wv, nw8);
    cvt_f16<<<nw8 / 256, 256>>>(w_o, wo, nw8);

    // projections
    dim3 gproj(D_ / 256, NROWS / 128);      // (4, 32)
    gemm_f16<2><<<gproj, 256, gemm_smem>>>(qc, wq, b_q, Qp, NROWS, D_, D_);
    gemm_f16<1><<<gproj, 256, gemm_smem>>>(kc, wk, b_k, Kp, NROWS, D_, D_);
    // V projection TRANSPOSED: C[dim][b*S+tok] = W_v A^T + b_v (row bias)
    dim3 gvt(NROWS / 256, D_ / 128);        // (16, 8)
    gemm_f16<3><<<gvt, 256, gemm_smem>>>(wv, vc, b_v, Vtp, D_, NROWS, D_);

    attn_f16<<<dim3(S_ / 256, B_ * H_), 512, attn_smem>>>(Qp, Kp, Vtp, Mp, Ap);

    gemm_f16<0><<<gproj, 256, gemm_smem>>>(Ap, wo, b_o, out, NROWS, D_, D_);
}

// round 12
// speedup vs baseline: 1.5643x; 1.5643x over previous
#include <cuda_runtime.h>
#include <cuda_fp16.h>
#include <cstdint>
#include <math.h>

#define B_   2
#define S_   2048
#define D_   1024
#define H_   16
#define DK_  64
#define NROWS (B_ * S_)   // 4096
#define NWORDS (S_ / 64)  // 32 u64 mask words per row

// Q pre-scale: (1/sqrt(DK)) * log2(e) so softmax can use raw ex2.
#define QSCALE 0.18033688011112043f

// Scratch (allocation-free rule: __device__ globals). All fp16.
__device__ __half g_Q[NROWS * D_];            // Q proj, pre-scaled by QSCALE
__device__ __half g_K[NROWS * D_];            // K proj
__device__ __half g_Vt[(size_t)D_ * NROWS];   // V proj TRANSPOSED: [dim][b*S+tok]
__device__ __half g_A[NROWS * D_];            // attention out
__device__ __half g_qc[NROWS * D_];           // converted activations
__device__ __half g_kc[NROWS * D_];
__device__ __half g_vc[NROWS * D_];
__device__ __half g_wq[D_ * D_];              // converted weights
__device__ __half g_wk[D_ * D_];
__device__ __half g_wv[D_ * D_];
__device__ __half g_wo[D_ * D_];
__device__ unsigned long long g_mbits[(size_t)B_ * S_ * NWORDS];

// ---------------------------------------------------------------------------
// helpers
// ---------------------------------------------------------------------------
__device__ __forceinline__ void mma_f16(float* c, const uint32_t* a,
                                        uint32_t b0, uint32_t b1) {
    asm volatile(
        "mma.sync.aligned.m16n8k16.row.col.f32.f16.f16.f32 "
        "{%0,%1,%2,%3}, {%4,%5,%6,%7}, {%8,%9}, {%0,%1,%2,%3};\n"
        : "+f"(c[0]), "+f"(c[1]), "+f"(c[2]), "+f"(c[3])
        : "r"(a[0]), "r"(a[1]), "r"(a[2]), "r"(a[3]), "r"(b0), "r"(b1));
}

__device__ __forceinline__ void cp16(void* sdst, const void* gsrc) {
    uint32_t s = (uint32_t)__cvta_generic_to_shared(sdst);
    asm volatile("cp.async.ca.shared.global [%0], [%1], 16;\n" :: "r"(s), "l"(gsrc));
}
__device__ __forceinline__ uint32_t ld32(const __half* p) {
    return *(const uint32_t*)(const void*)p;
}
__device__ __forceinline__ void st32(__half* p, float lo, float hi) {
    __half2 h = __floats2half2_rn(lo, hi);
    *(__half2*)(void*)p = h;
}
__device__ __forceinline__ uint32_t packh2(float lo, float hi) {
    __half2 h = __floats2half2_rn(lo, hi);
    return *(uint32_t*)&h;
}
__device__ __forceinline__ float ex2(float x) {   // 2^x, approx
    float r;
    asm("ex2.approx.ftz.f32 %0, %1;" : "=f"(r) : "f"(x));
    return r;
}

// ---------------------------------------------------------------------------
// fp32 -> fp16 (RN) pre-pass: 8 elements per thread
// ---------------------------------------------------------------------------
__global__ void __launch_bounds__(256) cvt_f16(
    const float* __restrict__ src, __half* __restrict__ dst, int n8)
{
    int i = blockIdx.x * blockDim.x + threadIdx.x;
    if (i >= n8) return;
    const float4* s = (const float4*)src;
    float4 a = s[2 * i], b = s[2 * i + 1];
    union { __half2 h[4]; uint4 u; } o;
    o.h[0] = __floats2half2_rn(a.x, a.y);
    o.h[1] = __floats2half2_rn(a.z, a.w);
    o.h[2] = __floats2half2_rn(b.x, b.y);
    o.h[3] = __floats2half2_rn(b.z, b.w);
    ((uint4*)dst)[i] = o.u;
}

// ---------------------------------------------------------------------------
// mask [B,1,S,S] int32 -> bit-packed u64
// ---------------------------------------------------------------------------
__global__ void __launch_bounds__(256) pack_mask(
    const int* __restrict__ mask, unsigned long long* __restrict__ bits)
{
    int gw = (int)((blockIdx.x * blockDim.x + threadIdx.x) >> 5);
    int lane = threadIdx.x & 31;
    const int* src = mask + (size_t)gw * 64;
    unsigned lo = __ballot_sync(0xffffffffu, src[lane] != 0);
    unsigned hi = __ballot_sync(0xffffffffu, src[lane + 32] != 0);
    bits[gw] = ((unsigned long long)hi << 32) | lo;
}

// ---------------------------------------------------------------------------
// C[M, Nd] = A[M, K] @ W[Nd, K]^T + bias — fp16 mma (m16n8k16), 2-stage
// cp.async. Block 128(m) x 256(n), BK=32, 256 threads; warps 2x4, warp 64x64.
// UNCHANGED from the 385us kernel.
// MODE: 0 = fp32 out (col bias)     1 = fp16 out (col bias)
//       2 = fp16 out * QSCALE       3 = fp16 out, bias indexed by ROW
// ---------------------------------------------------------------------------
#define PH 40   // smem pitch in halves (80 B)
template <int MODE>
__global__ void __launch_bounds__(256) gemm_f16(
    const __half* __restrict__ A, const __half* __restrict__ W,
    const float* __restrict__ bias, void* __restrict__ Cv,
    int M, int Nd, int K)
{
    extern __shared__ __half smh[];
    __half* As = smh;                 // 2 * 128 * 40
    __half* Bs = smh + 2 * 128 * PH;  // 2 * 256 * 40

    const int tid  = threadIdx.x;
    const int lane = tid & 31, wid = tid >> 5;
    const int g = lane >> 2, t = lane & 3;
    const int wm = (wid >> 2) * 64;
    const int wn = (wid & 3) * 64;
    const int m0 = blockIdx.y * 128, n0 = blockIdx.x * 256;

    float acc[4][8][4];
    #pragma unroll
    for (int i = 0; i < 4; i++)
        #pragma unroll
        for (int j = 0; j < 8; j++)
            #pragma unroll
            for (int q = 0; q < 4; q++) acc[i][j][q] = 0.f;

    // prologue: stage 0
    {
        #pragma unroll
        for (int j = 0; j < 2; j++) {
            int idx = tid + 256 * j, r = idx >> 2, ch = (idx & 3) * 8;
            cp16(As + r * PH + ch, A + (size_t)(m0 + r) * K + ch);
        }
        #pragma unroll
        for (int j = 0; j < 4; j++) {
            int idx = tid + 256 * j, r = idx >> 2, ch = (idx & 3) * 8;
            cp16(Bs + r * PH + ch, W + (size_t)(n0 + r) * K + ch);
        }
        asm volatile("cp.async.commit_group;\n");
    }

    const int NS = K / 32;
    for (int s = 0; s < NS; s++) {
        asm volatile("cp.async.wait_group 0;\n");
        __syncthreads();
        if (s + 1 < NS) {
            int kt = (s + 1) * 32;
            __half* Ad = As + ((s + 1) & 1) * 128 * PH;
            __half* Bd = Bs + ((s + 1) & 1) * 256 * PH;
            #pragma unroll
            for (int j = 0; j < 2; j++) {
                int idx = tid + 256 * j, r = idx >> 2, ch = (idx & 3) * 8;
                cp16(Ad + r * PH + ch, A + (size_t)(m0 + r) * K + kt + ch);
            }
            #pragma unroll
            for (int j = 0; j < 4; j++) {
                int idx = tid + 256 * j, r = idx >> 2, ch = (idx & 3) * 8;
                cp16(Bd + r * PH + ch, W + (size_t)(n0 + r) * K + kt + ch);
            }
            asm volatile("cp.async.commit_group;\n");
        }
        const __half* Ab = As + (s & 1) * 128 * PH;
        const __half* Bb = Bs + (s & 1) * 256 * PH;

        #pragma unroll
        for (int ks = 0; ks < 2; ks++) {
            uint32_t af[4][4], bf[8][2];
            #pragma unroll
            for (int mt = 0; mt < 4; mt++) {
                int r = wm + mt * 16;
                af[mt][0] = ld32(Ab + (r + g)     * PH + ks * 16 + 2 * t);
                af[mt][1] = ld32(Ab + (r + g + 8) * PH + ks * 16 + 2 * t);
                af[mt][2] = ld32(Ab + (r + g)     * PH + ks * 16 + 2 * t + 8);
                af[mt][3] = ld32(Ab + (r + g + 8) * PH + ks * 16 + 2 * t + 8);
            }
            #pragma unroll
            for (int nt = 0; nt < 8; nt++) {
                int c = wn + nt * 8;
                bf[nt][0] = ld32(Bb + (c + g) * PH + ks * 16 + 2 * t);
                bf[nt][1] = ld32(Bb + (c + g) * PH + ks * 16 + 2 * t + 8);
            }
            #pragma unroll
            for (int mt = 0; mt < 4; mt++)
                #pragma unroll
                for (int nt = 0; nt < 8; nt++)
                    mma_f16(acc[mt][nt], af[mt], bf[nt][0], bf[nt][1]);
        }
    }

    // epilogue
    #pragma unroll
    for (int mt = 0; mt < 4; mt++) {
        int r0 = m0 + wm + mt * 16 + g;
        float br0 = 0.f, br8 = 0.f;
        if (MODE == 3) { br0 = bias[r0]; br8 = bias[r0 + 8]; }
        #pragma unroll
        for (int nt = 0; nt < 8; nt++) {
            int c = n0 + wn + nt * 8 + 2 * t;
            if (MODE == 0) {
                float* C = (float*)Cv;
                float2 bv = *(const float2*)(bias + c);
                *(float2*)(C + (size_t)r0 * Nd + c) =
                    make_float2(acc[mt][nt][0] + bv.x, acc[mt][nt][1] + bv.y);
                *(float2*)(C + (size_t)(r0 + 8) * Nd + c) =
                    make_float2(acc[mt][nt][2] + bv.x, acc[mt][nt][3] + bv.y);
            } else if (MODE == 1) {
                __half* C = (__half*)Cv;
                float2 bv = *(const float2*)(bias + c);
                st32(C + (size_t)r0 * Nd + c,
                     acc[mt][nt][0] + bv.x, acc[mt][nt][1] + bv.y);
                st32(C + (size_t)(r0 + 8) * Nd + c,
                     acc[mt][nt][2] + bv.x, acc[mt][nt][3] + bv.y);
            } else if (MODE == 2) {
                __half* C = (__half*)Cv;
                float2 bv = *(const float2*)(bias + c);
                st32(C + (size_t)r0 * Nd + c,
                     QSCALE * (acc[mt][nt][0] + bv.x), QSCALE * (acc[mt][nt][1] + bv.y));
                st32(C + (size_t)(r0 + 8) * Nd + c,
                     QSCALE * (acc[mt][nt][2] + bv.x), QSCALE * (acc[mt][nt][3] + bv.y));
            } else {
                __half* C = (__half*)Cv;
                st32(C + (size_t)r0 * Nd + c,
                     acc[mt][nt][0] + br0, acc[mt][nt][1] + br0);
                st32(C + (size_t)(r0 + 8) * Nd + c,
                     acc[mt][nt][2] + br8, acc[mt][nt][3] + br8);
            }
        }
    }
}

// ---------------------------------------------------------------------------
// Flash attention, fp16 mma. Br=256, 512 threads = 16 warps, 16 q-rows each.
// Scores arrive in log2 domain (Q pre-scaled by QSCALE) -> softmax uses raw
// ex2. P is re-packed sacc->half2 IN REGISTERS (C-frag layout == A-frag
// layout for P@V), so there is no P smem buffer at all.
// K staged [tok][dim]; V staged [dim][tok]; 2-stage cp.async ring.
// ---------------------------------------------------------------------------
#define APH 72   // smem pitch in halves (144 B)
__global__ void __launch_bounds__(512, 1) attn_f16(
    const __half* __restrict__ Qg, const __half* __restrict__ Kg,
    const __half* __restrict__ Vtg, const unsigned long long* __restrict__ mbits,
    __half* __restrict__ O)
{
    extern __shared__ __half smh[];
    __half* Qs = smh;                       // 256*72
    __half* Ks = Qs + 256 * APH;            // 2 * 64*72
    __half* Vs = Ks + 2 * 64 * APH;         // 2 * 64*72

    const int tid = threadIdx.x;
    const int lane = tid & 31, wid = tid >> 5;
    const int g = lane >> 2, t4 = lane & 3;
    const int w16 = wid * 16;
    const int bh = blockIdx.y, b = bh >> 4, h = bh & 15;
    const int q0 = blockIdx.x * 256;
    const int T = S_ / 64;                  // 32 KV tiles

    const __half* Kg0  = Kg  + ((size_t)(b * S_)) * D_ + h * DK_;
    const __half* Vtg0 = Vtg + (size_t)(h * DK_) * NROWS + b * S_;

    // prologue: stage KV tiles 0 and 1
    #pragma unroll
    for (int pt = 0; pt < 2; pt++) {
        int r = tid >> 3, ch = (tid & 7) * 8;
        cp16(Ks + pt * 64 * APH + r * APH + ch,
             Kg0 + (size_t)(pt * 64 + r) * D_ + ch);
        cp16(Vs + pt * 64 * APH + r * APH + ch,
             Vtg0 + (size_t)r * NROWS + pt * 64 + ch);
        asm volatile("cp.async.commit_group;\n");
    }
    // Q tile [256 x 64]
    {
        const __half* Qb = Qg + ((size_t)(b * S_ + q0)) * D_ + h * DK_;
        #pragma unroll
        for (int j = 0; j < 4; j++) {
            int idx = tid + 512 * j, r = idx >> 3, ch = (idx & 7) * 8;
            cp16(Qs + r * APH + ch, Qb + (size_t)r * D_ + ch);
        }
        asm volatile("cp.async.commit_group;\n");
    }
    asm volatile("cp.async.wait_group 0;\n");
    __syncthreads();

    // Q fragments (4 k16-steps)
    uint32_t qf[4][4];
    #pragma unroll
    for (int ks = 0; ks < 4; ks++) {
        qf[ks][0] = ld32(Qs + (w16 + g)     * APH + ks * 16 + 2 * t4);
        qf[ks][1] = ld32(Qs + (w16 + g + 8) * APH + ks * 16 + 2 * t4);
        qf[ks][2] = ld32(Qs + (w16 + g)     * APH + ks * 16 + 2 * t4 + 8);
        qf[ks][3] = ld32(Qs + (w16 + g + 8) * APH + ks * 16 + 2 * t4 + 8);
    }

    float oacc[8][4];
    #pragma unroll
    for (int i = 0; i < 8; i++)
        #pragma unroll
        for (int j = 0; j < 4; j++) oacc[i][j] = 0.f;
    float mr0 = -INFINITY, mr1 = -INFINITY, lr0 = 0.f, lr1 = 0.f;

    const unsigned long long* mrow0 =
        mbits + (size_t)(b * S_ + q0 + w16 + g) * NWORDS;
    const unsigned long long* mrow1 =
        mbits + (size_t)(b * S_ + q0 + w16 + g + 8) * NWORDS;

    for (int t = 0; t < T; t++) {
        int s = t & 1;
        unsigned long long mw0 = __ldg(mrow0 + t);
        unsigned long long mw1 = __ldg(mrow1 + t);

        if (t > 0) asm volatile("cp.async.wait_group 1;\n");
        __syncthreads();
        const __half* Kb = Ks + s * 64 * APH;
        const __half* Vb = Vs + s * 64 * APH;

        // S = Q K^T (log2-domain scores)
        float sacc[8][4];
        #pragma unroll
        for (int i = 0; i < 8; i++)
            #pragma unroll
            for (int j = 0; j < 4; j++) sacc[i][j] = 0.f;
        #pragma unroll
        for (int nt = 0; nt < 8; nt++) {
            #pragma unroll
            for (int ks = 0; ks < 4; ks++) {
                uint32_t b0 = ld32(Kb + (nt * 8 + g) * APH + ks * 16 + 2 * t4);
                uint32_t b1 = ld32(Kb + (nt * 8 + g) * APH + ks * 16 + 2 * t4 + 8);
                mma_f16(sacc[nt], qf[ks], b0, b1);
            }
        }

        // mask (bit test) + online softmax (base-2)
        float rm0 = -INFINITY, rm1 = -INFINITY;
        #pragma unroll
        for (int nt = 0; nt < 8; nt++) {
            int sh = nt * 8 + 2 * t4;
            sacc[nt][0] = ((mw0 >> sh) & 1ull)       ? sacc[nt][0] : -1e9f;
            sacc[nt][1] = ((mw0 >> (sh + 1)) & 1ull) ? sacc[nt][1] : -1e9f;
            sacc[nt][2] = ((mw1 >> sh) & 1ull)       ? sacc[nt][2] : -1e9f;
            sacc[nt][3] = ((mw1 >> (sh + 1)) & 1ull) ? sacc[nt][3] : -1e9f;
            rm0 = fmaxf(rm0, fmaxf(sacc[nt][0], sacc[nt][1]));
            rm1 = fmaxf(rm1, fmaxf(sacc[nt][2], sacc[nt][3]));
        }
        rm0 = fmaxf(rm0, __shfl_xor_sync(0xffffffffu, rm0, 1));
        rm0 = fmaxf(rm0, __shfl_xor_sync(0xffffffffu, rm0, 2));
        rm1 = fmaxf(rm1, __shfl_xor_sync(0xffffffffu, rm1, 1));
        rm1 = fmaxf(rm1, __shfl_xor_sync(0xffffffffu, rm1, 2));

        float mn0 = fmaxf(mr0, rm0), mn1 = fmaxf(mr1, rm1);
        float a0 = ex2(mr0 - mn0), a1 = ex2(mr1 - mn1);
        float rs0 = 0.f, rs1 = 0.f;
        uint32_t ph[8][2];   // P in A-fragment layout, packed half2
        #pragma unroll
        for (int nt = 0; nt < 8; nt++) {
            float p0 = ex2(sacc[nt][0] - mn0);
            float p1 = ex2(sacc[nt][1] - mn0);
            float p2 = ex2(sacc[nt][2] - mn1);
            float p3 = ex2(sacc[nt][3] - mn1);
            rs0 += p0 + p1; rs1 += p2 + p3;
            ph[nt][0] = packh2(p0, p1);
            ph[nt][1] = packh2(p2, p3);
        }
        rs0 += __shfl_xor_sync(0xffffffffu, rs0, 1);
        rs0 += __shfl_xor_sync(0xffffffffu, rs0, 2);
        rs1 += __shfl_xor_sync(0xffffffffu, rs1, 1);
        rs1 += __shfl_xor_sync(0xffffffffu, rs1, 2);
        lr0 = lr0 * a0 + rs0; lr1 = lr1 * a1 + rs1;
        mr0 = mn0; mr1 = mn1;
        #pragma unroll
        for (int nt = 0; nt < 8; nt++) {
            oacc[nt][0] *= a0; oacc[nt][1] *= a0;
            oacc[nt][2] *= a1; oacc[nt][3] *= a1;
        }

        // O += P @ V  (P straight from registers; V [dim][tok] b-frags)
        #pragma unroll
        for (int ks = 0; ks < 4; ks++) {
            uint32_t pa[4];
            pa[0] = ph[2 * ks][0];       // P(g,     16ks+2t4, +1)
            pa[1] = ph[2 * ks][1];       // P(g+8,   16ks+2t4, +1)
            pa[2] = ph[2 * ks + 1][0];   // P(g,   16ks+8+2t4, +1)
            pa[3] = ph[2 * ks + 1][1];   // P(g+8, 16ks+8+2t4, +1)
            #pragma unroll
            for (int nt = 0; nt < 8; nt++) {
                uint32_t b0 = ld32(Vb + (nt * 8 + g) * APH + ks * 16 + 2 * t4);
                uint32_t b1 = ld32(Vb + (nt * 8 + g) * APH + ks * 16 + 2 * t4 + 8);
                mma_f16(oacc[nt], pa, b0, b1);
            }
        }

        __syncthreads();              // all warps done reading stage s
        if (t + 2 < T) {              // refill stage s with tile t+2
            int r = tid >> 3, ch = (tid & 7) * 8;
            cp16(Ks + s * 64 * APH + r * APH + ch,
                 Kg0 + (size_t)((t + 2) * 64 + r) * D_ + ch);
            cp16(Vs + s * 64 * APH + r * APH + ch,
                 Vtg0 + (size_t)r * NROWS + (t + 2) * 64 + ch);
        }
        asm volatile("cp.async.commit_group;\n");   // real or empty: uniform accounting
    }

    // write normalized output (fp16, consumed by final GEMM)
    float i0 = 1.f / lr0, i1 = 1.f / lr1;
    #pragma unroll
    for (int nt = 0; nt < 8; nt++) {
        int c = h * DK_ + nt * 8 + 2 * t4;
        size_t r0 = (size_t)(b * S_ + q0 + w16 + g) * D_ + c;
        size_t r1 = (size_t)(b * S_ + q0 + w16 + g + 8) * D_ + c;
        st32(O + r0, oacc[nt][0] * i0, oacc[nt][1] * i0);
        st32(O + r1, oacc[nt][2] * i1, oacc[nt][3] * i1);
    }
}

// ---------------------------------------------------------------------------
extern "C" void kernel_launch(void* const* d_in, const int* in_sizes, int n_in,
                              void* d_out, int out_size)
{
    const float* q    = (const float*)d_in[0];
    const float* k    = (const float*)d_in[1];
    const float* v    = (const float*)d_in[2];
    const int*   mask = (const int*)  d_in[3];
    const float* w_q  = (const float*)d_in[4];
    const float* b_q  = (const float*)d_in[5];
    const float* w_k  = (const float*)d_in[6];
    const float* b_k  = (const float*)d_in[7];
    const float* w_v  = (const float*)d_in[8];
    const float* b_v  = (const float*)d_in[9];
    const float* w_o  = (const float*)d_in[10];
    const float* b_o  = (const float*)d_in[11];
    float* out = (float*)d_out;

    __half *Qp, *Kp, *Vtp, *Ap, *qc, *kc, *vc, *wq, *wk, *wv, *wo;
    unsigned long long* Mp;
    cudaGetSymbolAddress((void**)&Qp, g_Q);
    cudaGetSymbolAddress((void**)&Kp, g_K);
    cudaGetSymbolAddress((void**)&Vtp, g_Vt);
    cudaGetSymbolAddress((void**)&Ap, g_A);
    cudaGetSymbolAddress((void**)&qc, g_qc);
    cudaGetSymbolAddress((void**)&kc, g_kc);
    cudaGetSymbolAddress((void**)&vc, g_vc);
    cudaGetSymbolAddress((void**)&wq, g_wq);
    cudaGetSymbolAddress((void**)&wk, g_wk);
    cudaGetSymbolAddress((void**)&wv, g_wv);
    cudaGetSymbolAddress((void**)&wo, g_wo);
    cudaGetSymbolAddress((void**)&Mp, g_mbits);

    const int gemm_smem = 2 * (128 + 256) * PH * (int)sizeof(__half);   // 61440
    const int attn_smem = (256 * APH + 4 * 64 * APH) * (int)sizeof(__half); // 73728

    static bool attr_done = false;
    if (!attr_done) {
        cudaFuncSetAttribute(gemm_f16<0>,
            cudaFuncAttributeMaxDynamicSharedMemorySize, gemm_smem);
        cudaFuncSetAttribute(gemm_f16<1>,
            cudaFuncAttributeMaxDynamicSharedMemorySize, gemm_smem);
        cudaFuncSetAttribute(gemm_f16<2>,
            cudaFuncAttributeMaxDynamicSharedMemorySize, gemm_smem);
        cudaFuncSetAttribute(gemm_f16<3>,
            cudaFuncAttributeMaxDynamicSharedMemorySize, gemm_smem);
        cudaFuncSetAttribute(attn_f16,
            cudaFuncAttributeMaxDynamicSharedMemorySize, attn_smem);
        attr_done = true;
    }

    // pre-passes
    pack_mask<<<(B_ * S_ * NWORDS) / 8, 256>>>(mask, Mp);
    const int nact8 = NROWS * D_ / 8;
    const int nw8   = D_ * D_ / 8;
    cvt_f16<<<nact8 / 256, 256>>>(q, qc, nact8);
    cvt_f16<<<nact8 / 256, 256>>>(k, kc, nact8);
    cvt_f16<<<nact8 / 256, 256>>>(v, vc, nact8);
    cvt_f16<<<nw8 / 256, 256>>>(w_q, wq, nw8);
    cvt_f16<<<nw8 / 256, 256>>>(w_k, wk, nw8);
    cvt_f16<<<nw8 / 256, 256>>>(w_v, wv, nw8);
    cvt_f16<<<nw8 / 256, 256>>>(w_o, wo, nw8);

    // projections
    dim3 gproj(D_ / 256, NROWS / 128);      // (4, 32)
    gemm_f16<2><<<gproj, 256, gemm_smem>>>(qc, wq, b_q, Qp, NROWS, D_, D_);
    gemm_f16<1><<<gproj, 256, gemm_smem>>>(kc, wk, b_k, Kp, NROWS, D_, D_);
    // V projection TRANSPOSED: C[dim][b*S+tok] = W_v A^T + b_v (row bias)
    dim3 gvt(NROWS / 256, D_ / 128);        // (16, 8)
    gemm_f16<3><<<gvt, 256, gemm_smem>>>(wv, vc, b_v, Vtp, D_, NROWS, D_);

    attn_f16<<<dim3(S_ / 256, B_ * H_), 512, attn_smem>>>(Qp, Kp, Vtp, Mp, Ap);

    gemm_f16<0><<<gproj, 256, gemm_smem>>>(Ap, wo, b_o, out, NROWS, D_, D_);
}

// round 14
// speedup vs baseline: 1.6117x; 1.0303x over previous
#include <cuda_runtime.h>
#include <cuda_fp16.h>
#include <cstdint>
#include <math.h>

#define B_   2
#define S_   2048
#define D_   1024
#define H_   16
#define DK_  64
#define NROWS (B_ * S_)   // 4096
#define NWORDS (S_ / 64)  // 32 u64 mask words per row

// Q pre-scale: (1/sqrt(DK)) * log2(e) so softmax can use raw ex2.
#define QSCALE 0.18033688011112043f

// Scratch (allocation-free rule: __device__ globals). All fp16.
// PERM layout: within every 16-half block, pairs stored [P0 P4 P1 P5 P2 P6 P3 P7]
__device__ __half g_Q[NROWS * D_];            // Q proj, QSCALE, PERM
__device__ __half g_K[NROWS * D_];            // K proj, PERM
__device__ __half g_Vt[(size_t)D_ * NROWS];   // V proj transposed [dim][b*S+tok], PERM
__device__ __half g_A[NROWS * D_];            // attention out, PERM
__device__ __half g_qc[NROWS * D_];           // converted activations, PERM
__device__ __half g_kc[NROWS * D_];
__device__ __half g_vc[NROWS * D_];
__device__ __half g_wq[D_ * D_];              // converted weights, PERM
__device__ __half g_wk[D_ * D_];
__device__ __half g_wv[D_ * D_];
__device__ __half g_wo[D_ * D_];
__device__ unsigned long long g_mbits[(size_t)B_ * S_ * NWORDS];

// ---------------------------------------------------------------------------
// helpers
// ---------------------------------------------------------------------------
__device__ __forceinline__ void mma_f16(float* c, const uint32_t* a,
                                        uint32_t b0, uint32_t b1) {
    asm volatile(
        "mma.sync.aligned.m16n8k16.row.col.f32.f16.f16.f32 "
        "{%0,%1,%2,%3}, {%4,%5,%6,%7}, {%8,%9}, {%0,%1,%2,%3};\n"
        : "+f"(c[0]), "+f"(c[1]), "+f"(c[2]), "+f"(c[3])
        : "r"(a[0]), "r"(a[1]), "r"(a[2]), "r"(a[3]), "r"(b0), "r"(b1));
}

__device__ __forceinline__ void cp16(void* sdst, const void* gsrc) {
    uint32_t s = (uint32_t)__cvta_generic_to_shared(sdst);
    asm volatile("cp.async.ca.shared.global [%0], [%1], 16;\n" :: "r"(s), "l"(gsrc));
}
__device__ __forceinline__ uint2 ld64(const __half* p) {   // LDS.64 (PERM pair)
    return *(const uint2*)(const void*)p;
}
__device__ __forceinline__ void st32(__half* p, float lo, float hi) {
    __half2 h = __floats2half2_rn(lo, hi);
    *(__half2*)(void*)p = h;
}
__device__ __forceinline__ uint32_t packh2(float lo, float hi) {
    __half2 h = __floats2half2_rn(lo, hi);
    return *(uint32_t*)&h;
}
__device__ __forceinline__ float ex2(float x) {
    float r;
    asm("ex2.approx.ftz.f32 %0, %1;" : "=f"(r) : "f"(x));
    return r;
}

// ---------------------------------------------------------------------------
// fp32 -> fp16 (RN) pre-pass with PERM: one 16-element block per thread.
// ---------------------------------------------------------------------------
__global__ void __launch_bounds__(256) cvt_f16p(
    const float* __restrict__ src, __half* __restrict__ dst, int n16)
{
    int i = blockIdx.x * blockDim.x + threadIdx.x;
    if (i >= n16) return;
    const float4* s = (const float4*)src + 4 * (size_t)i;
    float4 f0 = s[0], f1 = s[1], f2 = s[2], f3 = s[3];
    union { __half2 h[8]; uint4 u[2]; } o;
    o.h[0] = __floats2half2_rn(f0.x, f0.y);   // P0
    o.h[1] = __floats2half2_rn(f2.x, f2.y);   // P4
    o.h[2] = __floats2half2_rn(f0.z, f0.w);   // P1
    o.h[3] = __floats2half2_rn(f2.z, f2.w);   // P5
    o.h[4] = __floats2half2_rn(f1.x, f1.y);   // P2
    o.h[5] = __floats2half2_rn(f3.x, f3.y);   // P6
    o.h[6] = __floats2half2_rn(f1.z, f1.w);   // P3
    o.h[7] = __floats2half2_rn(f3.z, f3.w);   // P7
    uint4* d = (uint4*)dst + 2 * (size_t)i;
    d[0] = o.u[0]; d[1] = o.u[1];
}

// ---------------------------------------------------------------------------
// mask [B,1,S,S] int32 -> bit-packed u64
// ---------------------------------------------------------------------------
__global__ void __launch_bounds__(256) pack_mask(
    const int* __restrict__ mask, unsigned long long* __restrict__ bits)
{
    int gw = (int)((blockIdx.x * blockDim.x + threadIdx.x) >> 5);
    int lane = threadIdx.x & 31;
    const int* src = mask + (size_t)gw * 64;
    unsigned lo = __ballot_sync(0xffffffffu, src[lane] != 0);
    unsigned hi = __ballot_sync(0xffffffffu, src[lane + 32] != 0);
    bits[gw] = ((unsigned long long)hi << 32) | lo;
}

// ---------------------------------------------------------------------------
// C[M, Nd] = A[M, K] @ W[Nd, K]^T + bias — fp16 mma, 2-stage cp.async.
// Inputs A, W are PERM layout; fragment loads are LDS.64.
// Block 128(m) x 256(n), BK=32, 256 threads; warps 2x4, warp 64x64.
// MODE: 0 = fp32 out LINEAR (col bias)   1 = fp16 out PERM (col bias)
//       2 = fp16 out PERM * QSCALE       3 = fp16 out PERM, bias by ROW
// ---------------------------------------------------------------------------
#define PH 48   // pitch (halves); row stride 12 8B-groups -> LDS.64 conflict-free
template <int MODE>
__global__ void __launch_bounds__(256) gemm_f16(
    const __half* __restrict__ A, const __half* __restrict__ W,
    const float* __restrict__ bias, void* __restrict__ Cv,
    int M, int Nd, int K)
{
    extern __shared__ __half smh[];
    __half* As = smh;                 // 2 * 128 * 48
    __half* Bs = smh + 2 * 128 * PH;  // 2 * 256 * 48

    const int tid  = threadIdx.x;
    const int lane = tid & 31, wid = tid >> 5;
    const int g = lane >> 2, t = lane & 3;
    const int wm = (wid >> 2) * 64;
    const int wn = (wid & 3) * 64;
    const int m0 = blockIdx.y * 128, n0 = blockIdx.x * 256;

    float acc[4][8][4];
    #pragma unroll
    for (int i = 0; i < 4; i++)
        #pragma unroll
        for (int j = 0; j < 8; j++)
            #pragma unroll
            for (int q = 0; q < 4; q++) acc[i][j][q] = 0.f;

    // prologue: stage 0
    {
        #pragma unroll
        for (int j = 0; j < 2; j++) {
            int idx = tid + 256 * j, r = idx >> 2, ch = (idx & 3) * 8;
            cp16(As + r * PH + ch, A + (size_t)(m0 + r) * K + ch);
        }
        #pragma unroll
        for (int j = 0; j < 4; j++) {
            int idx = tid + 256 * j, r = idx >> 2, ch = (idx & 3) * 8;
            cp16(Bs + r * PH + ch, W + (size_t)(n0 + r) * K + ch);
        }
        asm volatile("cp.async.commit_group;\n");
    }

    const int NS = K / 32;
    for (int s = 0; s < NS; s++) {
        asm volatile("cp.async.wait_group 0;\n");
        __syncthreads();
        if (s + 1 < NS) {
            int kt = (s + 1) * 32;
            __half* Ad = As + ((s + 1) & 1) * 128 * PH;
            __half* Bd = Bs + ((s + 1) & 1) * 256 * PH;
            #pragma unroll
            for (int j = 0; j < 2; j++) {
                int idx = tid + 256 * j, r = idx >> 2, ch = (idx & 3) * 8;
                cp16(Ad + r * PH + ch, A + (size_t)(m0 + r) * K + kt + ch);
            }
            #pragma unroll
            for (int j = 0; j < 4; j++) {
                int idx = tid + 256 * j, r = idx >> 2, ch = (idx & 3) * 8;
                cp16(Bd + r * PH + ch, W + (size_t)(n0 + r) * K + kt + ch);
            }
            asm volatile("cp.async.commit_group;\n");
        }
        const __half* Ab = As + (s & 1) * 128 * PH;
        const __half* Bb = Bs + (s & 1) * 256 * PH;

        #pragma unroll
        for (int ks = 0; ks < 2; ks++) {
            uint32_t af[4][4], bf[8][2];
            #pragma unroll
            for (int mt = 0; mt < 4; mt++) {
                int r = wm + mt * 16;
                uint2 u0 = ld64(Ab + (r + g)     * PH + ks * 16 + 4 * t); // (a0,a2)
                uint2 u1 = ld64(Ab + (r + g + 8) * PH + ks * 16 + 4 * t); // (a1,a3)
                af[mt][0] = u0.x; af[mt][2] = u0.y;
                af[mt][1] = u1.x; af[mt][3] = u1.y;
            }
            #pragma unroll
            for (int nt = 0; nt < 8; nt++) {
                int c = wn + nt * 8;
                uint2 ub = ld64(Bb + (c + g) * PH + ks * 16 + 4 * t);     // (b0,b1)
                bf[nt][0] = ub.x; bf[nt][1] = ub.y;
            }
            #pragma unroll
            for (int mt = 0; mt < 4; mt++)
                #pragma unroll
                for (int nt = 0; nt < 8; nt++)
                    mma_f16(acc[mt][nt], af[mt], bf[nt][0], bf[nt][1]);
        }
    }

    // epilogue
    #pragma unroll
    for (int mt = 0; mt < 4; mt++) {
        int r0 = m0 + wm + mt * 16 + g;
        float br0 = 0.f, br8 = 0.f;
        if (MODE == 3) { br0 = bias[r0]; br8 = bias[r0 + 8]; }
        #pragma unroll
        for (int nt = 0; nt < 8; nt++) {
            int c = n0 + wn + nt * 8 + 2 * t;                 // logical column
            int cp = n0 + wn + (nt & ~1) * 8 + 4 * t + 2 * (nt & 1);  // PERM column
            if (MODE == 0) {
                float* C = (float*)Cv;
                float2 bv = *(const float2*)(bias + c);
                *(float2*)(C + (size_t)r0 * Nd + c) =
                    make_float2(acc[mt][nt][0] + bv.x, acc[mt][nt][1] + bv.y);
                *(float2*)(C + (size_t)(r0 + 8) * Nd + c) =
                    make_float2(acc[mt][nt][2] + bv.x, acc[mt][nt][3] + bv.y);
            } else if (MODE == 1) {
                __half* C = (__half*)Cv;
                float2 bv = *(const float2*)(bias + c);
                st32(C + (size_t)r0 * Nd + cp,
                     acc[mt][nt][0] + bv.x, acc[mt][nt][1] + bv.y);
                st32(C + (size_t)(r0 + 8) * Nd + cp,
                     acc[mt][nt][2] + bv.x, acc[mt][nt][3] + bv.y);
            } else if (MODE == 2) {
                __half* C = (__half*)Cv;
                float2 bv = *(const float2*)(bias + c);
                st32(C + (size_t)r0 * Nd + cp,
                     QSCALE * (acc[mt][nt][0] + bv.x), QSCALE * (acc[mt][nt][1] + bv.y));
                st32(C + (size_t)(r0 + 8) * Nd + cp,
                     QSCALE * (acc[mt][nt][2] + bv.x), QSCALE * (acc[mt][nt][3] + bv.y));
            } else {
                __half* C = (__half*)Cv;
                st32(C + (size_t)r0 * Nd + cp,
                     acc[mt][nt][0] + br0, acc[mt][nt][1] + br0);
                st32(C + (size_t)(r0 + 8) * Nd + cp,
                     acc[mt][nt][2] + br8, acc[mt][nt][3] + br8);
            }
        }
    }
}

// ---------------------------------------------------------------------------
// Flash attention, fp16 mma. Br=256, 512 threads = 16 warps, 16 q-rows each.
// Q/K/Vt arrive PERM -> every fragment load is one LDS.64. Log2-domain
// softmax (raw ex2); P stays in registers. K [tok][dim]; V [dim][tok];
// 2-stage cp.async ring. Output g_A written PERM (consumed by final GEMM).
// ---------------------------------------------------------------------------
#define APH 80   // pitch (halves) >= 64-half row; stride 20 8B-groups == 4 mod 16
__global__ void __launch_bounds__(512, 1) attn_f16(
    const __half* __restrict__ Qg, const __half* __restrict__ Kg,
    const __half* __restrict__ Vtg, const unsigned long long* __restrict__ mbits,
    __half* __restrict__ O)
{
    extern __shared__ __half smh[];
    __half* Qs = smh;                       // 256*80
    __half* Ks = Qs + 256 * APH;            // 2 * 64*80
    __half* Vs = Ks + 2 * 64 * APH;         // 2 * 64*80

    const int tid = threadIdx.x;
    const int lane = tid & 31, wid = tid >> 5;
    const int g = lane >> 2, t4 = lane & 3;
    const int w16 = wid * 16;
    const int bh = blockIdx.y, b = bh >> 4, h = bh & 15;
    const int q0 = blockIdx.x * 256;
    const int T = S_ / 64;                  // 32 KV tiles

    const __half* Kg0  = Kg  + ((size_t)(b * S_)) * D_ + h * DK_;
    const __half* Vtg0 = Vtg + (size_t)(h * DK_) * NROWS + b * S_;

    // prologue: stage KV tiles 0 and 1
    #pragma unroll
    for (int pt = 0; pt < 2; pt++) {
        int r = tid >> 3, ch = (tid & 7) * 8;
        cp16(Ks + pt * 64 * APH + r * APH + ch,
             Kg0 + (size_t)(pt * 64 + r) * D_ + ch);
        cp16(Vs + pt * 64 * APH + r * APH + ch,
             Vtg0 + (size_t)r * NROWS + pt * 64 + ch);
        asm volatile("cp.async.commit_group;\n");
    }
    // Q tile [256 x 64]
    {
        const __half* Qb = Qg + ((size_t)(b * S_ + q0)) * D_ + h * DK_;
        #pragma unroll
        for (int j = 0; j < 4; j++) {
            int idx = tid + 512 * j, r = idx >> 3, ch = (idx & 7) * 8;
            cp16(Qs + r * APH + ch, Qb + (size_t)r * D_ + ch);
        }
        asm volatile("cp.async.commit_group;\n");
    }
    asm volatile("cp.async.wait_group 0;\n");
    __syncthreads();

    // Q fragments (4 k16-steps), LDS.64 pairs
    uint32_t qf[4][4];
    #pragma unroll
    for (int ks = 0; ks < 4; ks++) {
        uint2 u0 = ld64(Qs + (w16 + g)     * APH + ks * 16 + 4 * t4);  // (a0,a2)
        uint2 u1 = ld64(Qs + (w16 + g + 8) * APH + ks * 16 + 4 * t4);  // (a1,a3)
        qf[ks][0] = u0.x; qf[ks][2] = u0.y;
        qf[ks][1] = u1.x; qf[ks][3] = u1.y;
    }

    float oacc[8][4];
    #pragma unroll
    for (int i = 0; i < 8; i++)
        #pragma unroll
        for (int j = 0; j < 4; j++) oacc[i][j] = 0.f;
    float mr0 = -INFINITY, mr1 = -INFINITY, lr0 = 0.f, lr1 = 0.f;

    const unsigned long long* mrow0 =
        mbits + (size_t)(b * S_ + q0 + w16 + g) * NWORDS;
    const unsigned long long* mrow1 =
        mbits + (size_t)(b * S_ + q0 + w16 + g + 8) * NWORDS;

    for (int t = 0; t < T; t++) {
        int s = t & 1;
        unsigned long long mw0 = __ldg(mrow0 + t);
        unsigned long long mw1 = __ldg(mrow1 + t);

        if (t > 0) asm volatile("cp.async.wait_group 1;\n");
        __syncthreads();
        const __half* Kb = Ks + s * 64 * APH;
        const __half* Vb = Vs + s * 64 * APH;

        // S = Q K^T (log2-domain scores)
        float sacc[8][4];
        #pragma unroll
        for (int i = 0; i < 8; i++)
            #pragma unroll
            for (int j = 0; j < 4; j++) sacc[i][j] = 0.f;
        #pragma unroll
        for (int nt = 0; nt < 8; nt++) {
            #pragma unroll
            for (int ks = 0; ks < 4; ks++) {
                uint2 ub = ld64(Kb + (nt * 8 + g) * APH + ks * 16 + 4 * t4);
                mma_f16(sacc[nt], qf[ks], ub.x, ub.y);
            }
        }

        // mask (bit test) + online softmax (base-2)
        float rm0 = -INFINITY, rm1 = -INFINITY;
        #pragma unroll
        for (int nt = 0; nt < 8; nt++) {
            int sh = nt * 8 + 2 * t4;
            sacc[nt][0] = ((mw0 >> sh) & 1ull)       ? sacc[nt][0] : -1e9f;
            sacc[nt][1] = ((mw0 >> (sh + 1)) & 1ull) ? sacc[nt][1] : -1e9f;
            sacc[nt][2] = ((mw1 >> sh) & 1ull)       ? sacc[nt][2] : -1e9f;
            sacc[nt][3] = ((mw1 >> (sh + 1)) & 1ull) ? sacc[nt][3] : -1e9f;
            rm0 = fmaxf(rm0, fmaxf(sacc[nt][0], sacc[nt][1]));
            rm1 = fmaxf(rm1, fmaxf(sacc[nt][2], sacc[nt][3]));
        }
        rm0 = fmaxf(rm0, __shfl_xor_sync(0xffffffffu, rm0, 1));
        rm0 = fmaxf(rm0, __shfl_xor_sync(0xffffffffu, rm0, 2));
        rm1 = fmaxf(rm1, __shfl_xor_sync(0xffffffffu, rm1, 1));
        rm1 = fmaxf(rm1, __shfl_xor_sync(0xffffffffu, rm1, 2));

        float mn0 = fmaxf(mr0, rm0), mn1 = fmaxf(mr1, rm1);
        float a0 = ex2(mr0 - mn0), a1 = ex2(mr1 - mn1);
        float rs0 = 0.f, rs1 = 0.f;
        uint32_t ph[8][2];   // P in A-fragment layout, packed half2
        #pragma unroll
        for (int nt = 0; nt < 8; nt++) {
            float p0 = ex2(sacc[nt][0] - mn0);
            float p1 = ex2(sacc[nt][1] - mn0);
            float p2 = ex2(sacc[nt][2] - mn1);
            float p3 = ex2(sacc[nt][3] - mn1);
            rs0 += p0 + p1; rs1 += p2 + p3;
            ph[nt][0] = packh2(p0, p1);
            ph[nt][1] = packh2(p2, p3);
        }
        rs0 += __shfl_xor_sync(0xffffffffu, rs0, 1);
        rs0 += __shfl_xor_sync(0xffffffffu, rs0, 2);
        rs1 += __shfl_xor_sync(0xffffffffu, rs1, 1);
        rs1 += __shfl_xor_sync(0xffffffffu, rs1, 2);
        lr0 = lr0 * a0 + rs0; lr1 = lr1 * a1 + rs1;
        mr0 = mn0; mr1 = mn1;
        #pragma unroll
        for (int nt = 0; nt < 8; nt++) {
            oacc[nt][0] *= a0; oacc[nt][1] *= a0;
            oacc[nt][2] *= a1; oacc[nt][3] *= a1;
        }

        // O += P @ V  (P from registers; V [dim][tok] PERM b-frags via LDS.64)
        #pragma unroll
        for (int ks = 0; ks < 4; ks++) {
            uint32_t pa[4];
            pa[0] = ph[2 * ks][0];
            pa[1] = ph[2 * ks][1];
            pa[2] = ph[2 * ks + 1][0];
            pa[3] = ph[2 * ks + 1][1];
            #pragma unroll
            for (int nt = 0; nt < 8; nt++) {
                uint2 ub = ld64(Vb + (nt * 8 + g) * APH + ks * 16 + 4 * t4);
                mma_f16(oacc[nt], pa, ub.x, ub.y);
            }
        }

        __syncthreads();              // all warps done reading stage s
        if (t + 2 < T) {              // refill stage s with tile t+2
            int r = tid >> 3, ch = (tid & 7) * 8;
            cp16(Ks + s * 64 * APH + r * APH + ch,
                 Kg0 + (size_t)((t + 2) * 64 + r) * D_ + ch);
            cp16(Vs + s * 64 * APH + r * APH + ch,
                 Vtg0 + (size_t)r * NROWS + (t + 2) * 64 + ch);
        }
        asm volatile("cp.async.commit_group;\n");   // real or empty: uniform accounting
    }

    // write normalized output in PERM layout (consumed by final GEMM)
    float i0 = 1.f / lr0, i1 = 1.f / lr1;
    #pragma unroll
    for (int nt = 0; nt < 8; nt++) {
        int cp = h * DK_ + (nt & ~1) * 8 + 4 * t4 + 2 * (nt & 1);
        size_t r0 = (size_t)(b * S_ + q0 + w16 + g) * D_ + cp;
        size_t r1 = (size_t)(b * S_ + q0 + w16 + g + 8) * D_ + cp;
        st32(O + r0, oacc[nt][0] * i0, oacc[nt][1] * i0);
        st32(O + r1, oacc[nt][2] * i1, oacc[nt][3] * i1);
    }
}

// ---------------------------------------------------------------------------
extern "C" void kernel_launch(void* const* d_in, const int* in_sizes, int n_in,
                              void* d_out, int out_size)
{
    const float* q    = (const float*)d_in[0];
    const float* k    = (const float*)d_in[1];
    const float* v    = (const float*)d_in[2];
    const int*   mask = (const int*)  d_in[3];
    const float* w_q  = (const float*)d_in[4];
    const float* b_q  = (const float*)d_in[5];
    const float* w_k  = (const float*)d_in[6];
    const float* b_k  = (const float*)d_in[7];
    const float* w_v  = (const float*)d_in[8];
    const float* b_v  = (const float*)d_in[9];
    const float* w_o  = (const float*)d_in[10];
    const float* b_o  = (const float*)d_in[11];
    float* out = (float*)d_out;

    __half *Qp, *Kp, *Vtp, *Ap, *qc, *kc, *vc, *wq, *wk, *wv, *wo;
    unsigned long long* Mp;
    cudaGetSymbolAddress((void**)&Qp, g_Q);
    cudaGetSymbolAddress((void**)&Kp, g_K);
    cudaGetSymbolAddress((void**)&Vtp, g_Vt);
    cudaGetSymbolAddress((void**)&Ap, g_A);
    cudaGetSymbolAddress((void**)&qc, g_qc);
    cudaGetSymbolAddress((void**)&kc, g_kc);
    cudaGetSymbolAddress((void**)&vc, g_vc);
    cudaGetSymbolAddress((void**)&wq, g_wq);
    cudaGetSymbolAddress((void**)&wk, g_wk);
    cudaGetSymbolAddress((void**)&wv, g_wv);
    cudaGetSymbolAddress((void**)&wo, g_wo);
    cudaGetSymbolAddress((void**)&Mp, g_mbits);

    const int gemm_smem = 2 * (128 + 256) * PH * (int)sizeof(__half);   // 73728
    const int attn_smem = (256 * APH + 4 * 64 * APH) * (int)sizeof(__half); // 81920

    static bool attr_done = false;
    if (!attr_done) {
        cudaFuncSetAttribute(gemm_f16<0>,
            cudaFuncAttributeMaxDynamicSharedMemorySize, gemm_smem);
        cudaFuncSetAttribute(gemm_f16<1>,
            cudaFuncAttributeMaxDynamicSharedMemorySize, gemm_smem);
        cudaFuncSetAttribute(gemm_f16<2>,
            cudaFuncAttributeMaxDynamicSharedMemorySize, gemm_smem);
        cudaFuncSetAttribute(gemm_f16<3>,
            cudaFuncAttributeMaxDynamicSharedMemorySize, gemm_smem);
        cudaFuncSetAttribute(attn_f16,
            cudaFuncAttributeMaxDynamicSharedMemorySize, attn_smem);
        attr_done = true;
    }

    // pre-passes (PERM-writing convert + mask pack)
    pack_mask<<<(B_ * S_ * NWORDS) / 8, 256>>>(mask, Mp);
    const int nact16 = NROWS * D_ / 16;   // 262144
    const int nw16   = D_ * D_ / 16;      //  65536
    cvt_f16p<<<nact16 / 256, 256>>>(q, qc, nact16);
    cvt_f16p<<<nact16 / 256, 256>>>(k, kc, nact16);
    cvt_f16p<<<nact16 / 256, 256>>>(v, vc, nact16);
    cvt_f16p<<<nw16 / 256, 256>>>(w_q, wq, nw16);
    cvt_f16p<<<nw16 / 256, 256>>>(w_k, wk, nw16);
    cvt_f16p<<<nw16 / 256, 256>>>(w_v, wv, nw16);
    cvt_f16p<<<nw16 / 256, 256>>>(w_o, wo, nw16);

    // projections
    dim3 gproj(D_ / 256, NROWS / 128);      // (4, 32)
    gemm_f16<2><<<gproj, 256, gemm_smem>>>(qc, wq, b_q, Qp, NROWS, D_, D_);
    gemm_f16<1><<<gproj, 256, gemm_smem>>>(kc, wk, b_k, Kp, NROWS, D_, D_);
    // V projection TRANSPOSED: C[dim][b*S+tok] = W_v A^T + b_v (row bias)
    dim3 gvt(NROWS / 256, D_ / 128);        // (16, 8)
    gemm_f16<3><<<gvt, 256, gemm_smem>>>(wv, vc, b_v, Vtp, D_, NROWS, D_);

    attn_f16<<<dim3(S_ / 256, B_ * H_), 512, attn_smem>>>(Qp, Kp, Vtp, Mp, Ap);

    gemm_f16<0><<<gproj, 256, gemm_smem>>>(Ap, wo, b_o, out, NROWS, D_, D_);
}

// round 16
// speedup vs baseline: 1.6395x; 1.0173x over previous
#include <cuda_runtime.h>
#include <cuda_fp16.h>
#include <cstdint>
#include <math.h>

#define B_   2
#define S_   2048
#define D_   1024
#define H_   16
#define DK_  64
#define NROWS (B_ * S_)   // 4096
#define NWORDS (S_ / 64)  // 32 u64 mask words per row

// Q pre-scale: (1/sqrt(DK)) * log2(e) so softmax can use raw ex2.
#define QSCALE 0.18033688011112043f

// Scratch (allocation-free rule: __device__ globals). All fp16.
// PERM layout: within every 16-half block, pairs stored [P0 P4 P1 P5 P2 P6 P3 P7]
__device__ __half g_Q[NROWS * D_];            // Q proj, QSCALE, PERM
__device__ __half g_K[NROWS * D_];            // K proj, PERM
__device__ __half g_Vt[(size_t)D_ * NROWS];   // V proj transposed [dim][b*S+tok], PERM
__device__ __half g_A[NROWS * D_];            // attention out, PERM
__device__ __half g_qc[NROWS * D_];           // converted activations, PERM
__device__ __half g_kc[NROWS * D_];
__device__ __half g_vc[NROWS * D_];
__device__ __half g_wq[D_ * D_];              // converted weights, PERM
__device__ __half g_wk[D_ * D_];
__device__ __half g_wv[D_ * D_];
__device__ __half g_wo[D_ * D_];
__device__ unsigned long long g_mbits[(size_t)B_ * S_ * NWORDS];

// ---------------------------------------------------------------------------
// helpers
// ---------------------------------------------------------------------------
__device__ __forceinline__ void mma_f16(float* c, const uint32_t* a,
                                        uint32_t b0, uint32_t b1) {
    asm volatile(
        "mma.sync.aligned.m16n8k16.row.col.f32.f16.f16.f32 "
        "{%0,%1,%2,%3}, {%4,%5,%6,%7}, {%8,%9}, {%0,%1,%2,%3};\n"
        : "+f"(c[0]), "+f"(c[1]), "+f"(c[2]), "+f"(c[3])
        : "r"(a[0]), "r"(a[1]), "r"(a[2]), "r"(a[3]), "r"(b0), "r"(b1));
}

__device__ __forceinline__ void cp16(void* sdst, const void* gsrc) {
    uint32_t s = (uint32_t)__cvta_generic_to_shared(sdst);
    asm volatile("cp.async.ca.shared.global [%0], [%1], 16;\n" :: "r"(s), "l"(gsrc));
}
__device__ __forceinline__ uint2 ld64(const __half* p) {   // LDS.64 (PERM pair)
    return *(const uint2*)(const void*)p;
}
__device__ __forceinline__ void st32(__half* p, float lo, float hi) {
    __half2 h = __floats2half2_rn(lo, hi);
    *(__half2*)(void*)p = h;
}
__device__ __forceinline__ uint32_t packh2(float lo, float hi) {
    __half2 h = __floats2half2_rn(lo, hi);
    return *(uint32_t*)&h;
}
__device__ __forceinline__ float ex2(float x) {
    float r;
    asm("ex2.approx.ftz.f32 %0, %1;" : "=f"(r) : "f"(x));
    return r;
}

// ---------------------------------------------------------------------------
// fp32 -> fp16 (RN) pre-pass with PERM: one 16-element block per thread.
// ---------------------------------------------------------------------------
__global__ void __launch_bounds__(256) cvt_f16p(
    const float* __restrict__ src, __half* __restrict__ dst, int n16)
{
    int i = blockIdx.x * blockDim.x + threadIdx.x;
    if (i >= n16) return;
    const float4* s = (const float4*)src + 4 * (size_t)i;
    float4 f0 = s[0], f1 = s[1], f2 = s[2], f3 = s[3];
    union { __half2 h[8]; uint4 u[2]; } o;
    o.h[0] = __floats2half2_rn(f0.x, f0.y);   // P0
    o.h[1] = __floats2half2_rn(f2.x, f2.y);   // P4
    o.h[2] = __floats2half2_rn(f0.z, f0.w);   // P1
    o.h[3] = __floats2half2_rn(f2.z, f2.w);   // P5
    o.h[4] = __floats2half2_rn(f1.x, f1.y);   // P2
    o.h[5] = __floats2half2_rn(f3.x, f3.y);   // P6
    o.h[6] = __floats2half2_rn(f1.z, f1.w);   // P3
    o.h[7] = __floats2half2_rn(f3.z, f3.w);   // P7
    uint4* d = (uint4*)dst + 2 * (size_t)i;
    d[0] = o.u[0]; d[1] = o.u[1];
}

// ---------------------------------------------------------------------------
// mask [B,1,S,S] int32 -> bit-packed u64
// ---------------------------------------------------------------------------
__global__ void __launch_bounds__(256) pack_mask(
    const int* __restrict__ mask, unsigned long long* __restrict__ bits)
{
    int gw = (int)((blockIdx.x * blockDim.x + threadIdx.x) >> 5);
    int lane = threadIdx.x & 31;
    const int* src = mask + (size_t)gw * 64;
    unsigned lo = __ballot_sync(0xffffffffu, src[lane] != 0);
    unsigned hi = __ballot_sync(0xffffffffu, src[lane + 32] != 0);
    bits[gw] = ((unsigned long long)hi << 32) | lo;
}

// ---------------------------------------------------------------------------
// C[M, Nd] = A[M, K] @ W[Nd, K]^T + bias — fp16 mma, 3-stage cp.async.
// Inputs A, W are PERM layout; fragment loads are LDS.64.
// Block 128(m) x 256(n), BK=32, 256 threads; warps 2x4, warp 64x64.
// MODE: 0 = fp32 out LINEAR (col bias)   1 = fp16 out PERM (col bias)
//       2 = fp16 out PERM * QSCALE       3 = fp16 out PERM, bias by ROW
// ---------------------------------------------------------------------------
#define PH 48   // pitch (halves); row stride 12 8B-groups -> LDS.64 conflict-free
template <int MODE>
__global__ void __launch_bounds__(256) gemm_f16(
    const __half* __restrict__ A, const __half* __restrict__ W,
    const float* __restrict__ bias, void* __restrict__ Cv,
    int M, int Nd, int K)
{
    extern __shared__ __half smh[];
    __half* As = smh;                 // 3 * 128 * 48
    __half* Bs = smh + 3 * 128 * PH;  // 3 * 256 * 48

    const int tid  = threadIdx.x;
    const int lane = tid & 31, wid = tid >> 5;
    const int g = lane >> 2, t = lane & 3;
    const int wm = (wid >> 2) * 64;
    const int wn = (wid & 3) * 64;
    const int m0 = blockIdx.y * 128, n0 = blockIdx.x * 256;

    float acc[4][8][4];
    #pragma unroll
    for (int i = 0; i < 4; i++)
        #pragma unroll
        for (int j = 0; j < 8; j++)
            #pragma unroll
            for (int q = 0; q < 4; q++) acc[i][j][q] = 0.f;

    // prologue: stages 0, 1
    #pragma unroll
    for (int ps = 0; ps < 2; ps++) {
        int kt = ps * 32;
        __half* Ad = As + ps * 128 * PH;
        __half* Bd = Bs + ps * 256 * PH;
        #pragma unroll
        for (int j = 0; j < 2; j++) {
            int idx = tid + 256 * j, r = idx >> 2, ch = (idx & 3) * 8;
            cp16(Ad + r * PH + ch, A + (size_t)(m0 + r) * K + kt + ch);
        }
        #pragma unroll
        for (int j = 0; j < 4; j++) {
            int idx = tid + 256 * j, r = idx >> 2, ch = (idx & 3) * 8;
            cp16(Bd + r * PH + ch, W + (size_t)(n0 + r) * K + kt + ch);
        }
        asm volatile("cp.async.commit_group;\n");
    }

    const int NS = K / 32;
    for (int s = 0; s < NS; s++) {
        if (s < NS - 1) asm volatile("cp.async.wait_group 1;\n");
        else            asm volatile("cp.async.wait_group 0;\n");
        __syncthreads();

        if (s + 2 < NS) {
            int kt = (s + 2) * 32;
            __half* Ad = As + ((s + 2) % 3) * 128 * PH;
            __half* Bd = Bs + ((s + 2) % 3) * 256 * PH;
            #pragma unroll
            for (int j = 0; j < 2; j++) {
                int idx = tid + 256 * j, r = idx >> 2, ch = (idx & 3) * 8;
                cp16(Ad + r * PH + ch, A + (size_t)(m0 + r) * K + kt + ch);
            }
            #pragma unroll
            for (int j = 0; j < 4; j++) {
                int idx = tid + 256 * j, r = idx >> 2, ch = (idx & 3) * 8;
                cp16(Bd + r * PH + ch, W + (size_t)(n0 + r) * K + kt + ch);
            }
            asm volatile("cp.async.commit_group;\n");
        } else {
            asm volatile("cp.async.commit_group;\n");   // empty: uniform accounting
        }

        const __half* Ab = As + (s % 3) * 128 * PH;
        const __half* Bb = Bs + (s % 3) * 256 * PH;

        #pragma unroll
        for (int ks = 0; ks < 2; ks++) {
            uint32_t af[4][4], bf[8][2];
            #pragma unroll
            for (int mt = 0; mt < 4; mt++) {
                int r = wm + mt * 16;
                uint2 u0 = ld64(Ab + (r + g)     * PH + ks * 16 + 4 * t); // (a0,a2)
                uint2 u1 = ld64(Ab + (r + g + 8) * PH + ks * 16 + 4 * t); // (a1,a3)
                af[mt][0] = u0.x; af[mt][2] = u0.y;
                af[mt][1] = u1.x; af[mt][3] = u1.y;
            }
            #pragma unroll
            for (int nt = 0; nt < 8; nt++) {
                int c = wn + nt * 8;
                uint2 ub = ld64(Bb + (c + g) * PH + ks * 16 + 4 * t);     // (b0,b1)
                bf[nt][0] = ub.x; bf[nt][1] = ub.y;
            }
            #pragma unroll
            for (int mt = 0; mt < 4; mt++)
                #pragma unroll
                for (int nt = 0; nt < 8; nt++)
                    mma_f16(acc[mt][nt], af[mt], bf[nt][0], bf[nt][1]);
        }
    }

    // epilogue
    #pragma unroll
    for (int mt = 0; mt < 4; mt++) {
        int r0 = m0 + wm + mt * 16 + g;
        float br0 = 0.f, br8 = 0.f;
        if (MODE == 3) { br0 = bias[r0]; br8 = bias[r0 + 8]; }
        #pragma unroll
        for (int nt = 0; nt < 8; nt++) {
            int c = n0 + wn + nt * 8 + 2 * t;                 // logical column
            int cp = n0 + wn + (nt & ~1) * 8 + 4 * t + 2 * (nt & 1);  // PERM column
            if (MODE == 0) {
                float* C = (float*)Cv;
                float2 bv = *(const float2*)(bias + c);
                *(float2*)(C + (size_t)r0 * Nd + c) =
                    make_float2(acc[mt][nt][0] + bv.x, acc[mt][nt][1] + bv.y);
                *(float2*)(C + (size_t)(r0 + 8) * Nd + c) =
                    make_float2(acc[mt][nt][2] + bv.x, acc[mt][nt][3] + bv.y);
            } else if (MODE == 1) {
                __half* C = (__half*)Cv;
                float2 bv = *(const float2*)(bias + c);
                st32(C + (size_t)r0 * Nd + cp,
                     acc[mt][nt][0] + bv.x, acc[mt][nt][1] + bv.y);
                st32(C + (size_t)(r0 + 8) * Nd + cp,
                     acc[mt][nt][2] + bv.x, acc[mt][nt][3] + bv.y);
            } else if (MODE == 2) {
                __half* C = (__half*)Cv;
                float2 bv = *(const float2*)(bias + c);
                st32(C + (size_t)r0 * Nd + cp,
                     QSCALE * (acc[mt][nt][0] + bv.x), QSCALE * (acc[mt][nt][1] + bv.y));
                st32(C + (size_t)(r0 + 8) * Nd + cp,
                     QSCALE * (acc[mt][nt][2] + bv.x), QSCALE * (acc[mt][nt][3] + bv.y));
            } else {
                __half* C = (__half*)Cv;
                st32(C + (size_t)r0 * Nd + cp,
                     acc[mt][nt][0] + br0, acc[mt][nt][1] + br0);
                st32(C + (size_t)(r0 + 8) * Nd + cp,
                     acc[mt][nt][2] + br8, acc[mt][nt][3] + br8);
            }
        }
    }
}

// ---------------------------------------------------------------------------
// Flash attention, fp16 mma. Br=256, 512 threads = 16 warps, 16 q-rows each.
// PERM inputs -> LDS.64 fragment loads. Log2-domain softmax (ex2); P stays
// in registers. 3-stage KV ring, ONE __syncthreads per tile (refill target
// (t+2)%3 was drained by the iteration-top barrier). Mask words pre-shifted
// by 2*t4 once per tile -> per-nt gating is constant u32 shift + and + sel.
// ---------------------------------------------------------------------------
#define APH 80   // pitch (halves); stride 20 8B-groups == 4 mod 16 -> conflict-free
#define NST 3
__global__ void __launch_bounds__(512, 1) attn_f16(
    const __half* __restrict__ Qg, const __half* __restrict__ Kg,
    const __half* __restrict__ Vtg, const unsigned long long* __restrict__ mbits,
    __half* __restrict__ O)
{
    extern __shared__ __half smh[];
    __half* Qs = smh;                       // 256*80
    __half* Ks = Qs + 256 * APH;            // NST * 64*80
    __half* Vs = Ks + NST * 64 * APH;       // NST * 64*80

    const int tid = threadIdx.x;
    const int lane = tid & 31, wid = tid >> 5;
    const int g = lane >> 2, t4 = lane & 3;
    const int w16 = wid * 16;
    const int bh = blockIdx.y, b = bh >> 4, h = bh & 15;
    const int q0 = blockIdx.x * 256;
    const int T = S_ / 64;                  // 32 KV tiles

    const __half* Kg0  = Kg  + ((size_t)(b * S_)) * D_ + h * DK_;
    const __half* Vtg0 = Vtg + (size_t)(h * DK_) * NROWS + b * S_;

    // prologue: stage KV tiles 0 and 1
    #pragma unroll
    for (int pt = 0; pt < 2; pt++) {
        int r = tid >> 3, ch = (tid & 7) * 8;
        cp16(Ks + pt * 64 * APH + r * APH + ch,
             Kg0 + (size_t)(pt * 64 + r) * D_ + ch);
        cp16(Vs + pt * 64 * APH + r * APH + ch,
             Vtg0 + (size_t)r * NROWS + pt * 64 + ch);
        asm volatile("cp.async.commit_group;\n");
    }
    // Q tile [256 x 64] (counts as one more group; drained by wait_group 0)
    {
        const __half* Qb = Qg + ((size_t)(b * S_ + q0)) * D_ + h * DK_;
        #pragma unroll
        for (int j = 0; j < 4; j++) {
            int idx = tid + 512 * j, r = idx >> 3, ch = (idx & 7) * 8;
            cp16(Qs + r * APH + ch, Qb + (size_t)r * D_ + ch);
        }
        asm volatile("cp.async.commit_group;\n");
    }
    asm volatile("cp.async.wait_group 0;\n");
    __syncthreads();

    // Q fragments (4 k16-steps), LDS.64 pairs
    uint32_t qf[4][4];
    #pragma unroll
    for (int ks = 0; ks < 4; ks++) {
        uint2 u0 = ld64(Qs + (w16 + g)     * APH + ks * 16 + 4 * t4);  // (a0,a2)
        uint2 u1 = ld64(Qs + (w16 + g + 8) * APH + ks * 16 + 4 * t4);  // (a1,a3)
        qf[ks][0] = u0.x; qf[ks][2] = u0.y;
        qf[ks][1] = u1.x; qf[ks][3] = u1.y;
    }

    float oacc[8][4];
    #pragma unroll
    for (int i = 0; i < 8; i++)
        #pragma unroll
        for (int j = 0; j < 4; j++) oacc[i][j] = 0.f;
    float mr0 = -INFINITY, mr1 = -INFINITY, lr0 = 0.f, lr1 = 0.f;

    const unsigned long long* mrow0 =
        mbits + (size_t)(b * S_ + q0 + w16 + g) * NWORDS;
    const unsigned long long* mrow1 =
        mbits + (size_t)(b * S_ + q0 + w16 + g + 8) * NWORDS;
    const int tsh = 2 * t4;

    for (int t = 0; t < T; t++) {
        int s = t % NST;
        unsigned long long mw0 = __ldg(mrow0 + t) >> tsh;
        unsigned long long mw1 = __ldg(mrow1 + t) >> tsh;
        uint32_t lo0 = (uint32_t)mw0, hi0 = (uint32_t)(mw0 >> 32);
        uint32_t lo1 = (uint32_t)mw1, hi1 = (uint32_t)(mw1 >> 32);

        // wait for tile t (2 tiles in flight after its commit)
        asm volatile("cp.async.wait_group 1;\n");
        __syncthreads();   // also guarantees stage (t+2)%3 fully drained

        // refill stage (t+2)%NST with tile t+2, overlapped with compute
        if (t + 2 < T) {
            int s2 = (t + 2) % NST;
            int r = tid >> 3, ch = (tid & 7) * 8;
            cp16(Ks + s2 * 64 * APH + r * APH + ch,
                 Kg0 + (size_t)((t + 2) * 64 + r) * D_ + ch);
            cp16(Vs + s2 * 64 * APH + r * APH + ch,
                 Vtg0 + (size_t)r * NROWS + (t + 2) * 64 + ch);
        }
        asm volatile("cp.async.commit_group;\n");   // real or empty

        const __half* Kb = Ks + s * 64 * APH;
        const __half* Vb = Vs + s * 64 * APH;

        // S = Q K^T (log2-domain scores)
        float sacc[8][4];
        #pragma unroll
        for (int i = 0; i < 8; i++)
            #pragma unroll
            for (int j = 0; j < 4; j++) sacc[i][j] = 0.f;
        #pragma unroll
        for (int nt = 0; nt < 8; nt++) {
            #pragma unroll
            for (int ks = 0; ks < 4; ks++) {
                uint2 ub = ld64(Kb + (nt * 8 + g) * APH + ks * 16 + 4 * t4);
                mma_f16(sacc[nt], qf[ks], ub.x, ub.y);
            }
        }

        // mask (constant u32 shifts) + online softmax (base-2)
        float rm0 = -INFINITY, rm1 = -INFINITY;
        #pragma unroll
        for (int nt = 0; nt < 8; nt++) {
            uint32_t b0 = (nt < 4) ? (lo0 >> (nt * 8)) : (hi0 >> ((nt - 4) * 8));
            uint32_t b1 = (nt < 4) ? (lo1 >> (nt * 8)) : (hi1 >> ((nt - 4) * 8));
            sacc[nt][0] = (b0 & 1u) ? sacc[nt][0] : -1e9f;
            sacc[nt][1] = (b0 & 2u) ? sacc[nt][1] : -1e9f;
            sacc[nt][2] = (b1 & 1u) ? sacc[nt][2] : -1e9f;
            sacc[nt][3] = (b1 & 2u) ? sacc[nt][3] : -1e9f;
            rm0 = fmaxf(rm0, fmaxf(sacc[nt][0], sacc[nt][1]));
            rm1 = fmaxf(rm1, fmaxf(sacc[nt][2], sacc[nt][3]));
        }
        rm0 = fmaxf(rm0, __shfl_xor_sync(0xffffffffu, rm0, 1));
        rm0 = fmaxf(rm0, __shfl_xor_sync(0xffffffffu, rm0, 2));
        rm1 = fmaxf(rm1, __shfl_xor_sync(0xffffffffu, rm1, 1));
        rm1 = fmaxf(rm1, __shfl_xor_sync(0xffffffffu, rm1, 2));

        float mn0 = fmaxf(mr0, rm0), mn1 = fmaxf(mr1, rm1);
        float a0 = ex2(mr0 - mn0), a1 = ex2(mr1 - mn1);
        float rs0 = 0.f, rs1 = 0.f;
        uint32_t ph[8][2];   // P in A-fragment layout, packed half2
        #pragma unroll
        for (int nt = 0; nt < 8; nt++) {
            float p0 = ex2(sacc[nt][0] - mn0);
            float p1 = ex2(sacc[nt][1] - mn0);
            float p2 = ex2(sacc[nt][2] - mn1);
            float p3 = ex2(sacc[nt][3] - mn1);
            rs0 += p0 + p1; rs1 += p2 + p3;
            ph[nt][0] = packh2(p0, p1);
            ph[nt][1] = packh2(p2, p3);
        }
        rs0 += __shfl_xor_sync(0xffffffffu, rs0, 1);
        rs0 += __shfl_xor_sync(0xffffffffu, rs0, 2);
        rs1 += __shfl_xor_sync(0xffffffffu, rs1, 1);
        rs1 += __shfl_xor_sync(0xffffffffu, rs1, 2);
        lr0 = lr0 * a0 + rs0; lr1 = lr1 * a1 + rs1;
        mr0 = mn0; mr1 = mn1;
        #pragma unroll
        for (int nt = 0; nt < 8; nt++) {
            oacc[nt][0] *= a0; oacc[nt][1] *= a0;
            oacc[nt][2] *= a1; oacc[nt][3] *= a1;
        }

        // O += P @ V  (P from registers; V [dim][tok] PERM b-frags via LDS.64)
        #pragma unroll
        for (int ks = 0; ks < 4; ks++) {
            uint32_t pa[4];
            pa[0] = ph[2 * ks][0];
            pa[1] = ph[2 * ks][1];
            pa[2] = ph[2 * ks + 1][0];
            pa[3] = ph[2 * ks + 1][1];
            #pragma unroll
            for (int nt = 0; nt < 8; nt++) {
                uint2 ub = ld64(Vb + (nt * 8 + g) * APH + ks * 16 + 4 * t4);
                mma_f16(oacc[nt], pa, ub.x, ub.y);
            }
        }
    }

    // write normalized output in PERM layout (consumed by final GEMM)
    float i0 = 1.f / lr0, i1 = 1.f / lr1;
    #pragma unroll
    for (int nt = 0; nt < 8; nt++) {
        int cp = h * DK_ + (nt & ~1) * 8 + 4 * t4 + 2 * (nt & 1);
        size_t r0 = (size_t)(b * S_ + q0 + w16 + g) * D_ + cp;
        size_t r1 = (size_t)(b * S_ + q0 + w16 + g + 8) * D_ + cp;
        st32(O + r0, oacc[nt][0] * i0, oacc[nt][1] * i0);
        st32(O + r1, oacc[nt][2] * i1, oacc[nt][3] * i1);
    }
}

// ---------------------------------------------------------------------------
extern "C" void kernel_launch(void* const* d_in, const int* in_sizes, int n_in,
                              void* d_out, int out_size)
{
    const float* q    = (const float*)d_in[0];
    const float* k    = (const float*)d_in[1];
    const float* v    = (const float*)d_in[2];
    const int*   mask = (const int*)  d_in[3];
    const float* w_q  = (const float*)d_in[4];
    const float* b_q  = (const float*)d_in[5];
    const float* w_k  = (const float*)d_in[6];
    const float* b_k  = (const float*)d_in[7];
    const float* w_v  = (const float*)d_in[8];
    const float* b_v  = (const float*)d_in[9];
    const float* w_o  = (const float*)d_in[10];
    const float* b_o  = (const float*)d_in[11];
    float* out = (float*)d_out;

    __half *Qp, *Kp, *Vtp, *Ap, *qc, *kc, *vc, *wq, *wk, *wv, *wo;
    unsigned long long* Mp;
    cudaGetSymbolAddress((void**)&Qp, g_Q);
    cudaGetSymbolAddress((void**)&Kp, g_K);
    cudaGetSymbolAddress((void**)&Vtp, g_Vt);
    cudaGetSymbolAddress((void**)&Ap, g_A);
    cudaGetSymbolAddress((void**)&qc, g_qc);
    cudaGetSymbolAddress((void**)&kc, g_kc);
    cudaGetSymbolAddress((void**)&vc, g_vc);
    cudaGetSymbolAddress((void**)&wq, g_wq);
    cudaGetSymbolAddress((void**)&wk, g_wk);
    cudaGetSymbolAddress((void**)&wv, g_wv);
    cudaGetSymbolAddress((void**)&wo, g_wo);
    cudaGetSymbolAddress((void**)&Mp, g_mbits);

    const int gemm_smem = 3 * (128 + 256) * PH * (int)sizeof(__half);   // 110592
    const int attn_smem = (256 * APH + 2 * NST * 64 * APH) * (int)sizeof(__half); // 102400

    static bool attr_done = false;
    if (!attr_done) {
        cudaFuncSetAttribute(gemm_f16<0>,
            cudaFuncAttributeMaxDynamicSharedMemorySize, gemm_smem);
        cudaFuncSetAttribute(gemm_f16<1>,
            cudaFuncAttributeMaxDynamicSharedMemorySize, gemm_smem);
        cudaFuncSetAttribute(gemm_f16<2>,
            cudaFuncAttributeMaxDynamicSharedMemorySize, gemm_smem);
        cudaFuncSetAttribute(gemm_f16<3>,
            cudaFuncAttributeMaxDynamicSharedMemorySize, gemm_smem);
        cudaFuncSetAttribute(attn_f16,
            cudaFuncAttributeMaxDynamicSharedMemorySize, attn_smem);
        attr_done = true;
    }

    // pre-passes (PERM-writing convert + mask pack)
    pack_mask<<<(B_ * S_ * NWORDS) / 8, 256>>>(mask, Mp);
    const int nact16 = NROWS * D_ / 16;   // 262144
    const int nw16   = D_ * D_ / 16;      //  65536
    cvt_f16p<<<nact16 / 256, 256>>>(q, qc, nact16);
    cvt_f16p<<<nact16 / 256, 256>>>(k, kc, nact16);
    cvt_f16p<<<nact16 / 256, 256>>>(v, vc, nact16);
    cvt_f16p<<<nw16 / 256, 256>>>(w_q, wq, nw16);
    cvt_f16p<<<nw16 / 256, 256>>>(w_k, wk, nw16);
    cvt_f16p<<<nw16 / 256, 256>>>(w_v, wv, nw16);
    cvt_f16p<<<nw16 / 256, 256>>>(w_o, wo, nw16);

    // projections
    dim3 gproj(D_ / 256, NROWS / 128);      // (4, 32)
    gemm_f16<2><<<gproj, 256, gemm_smem>>>(qc, wq, b_q, Qp, NROWS, D_, D_);
    gemm_f16<1><<<gproj, 256, gemm_smem>>>(kc, wk, b_k, Kp, NROWS, D_, D_);
    // V projection TRANSPOSED: C[dim][b*S+tok] = W_v A^T + b_v (row bias)
    dim3 gvt(NROWS / 256, D_ / 128);        // (16, 8)
    gemm_f16<3><<<gvt, 256, gemm_smem>>>(wv, vc, b_v, Vtp, D_, NROWS, D_);

    attn_f16<<<dim3(S_ / 256, B_ * H_), 512, attn_smem>>>(Qp, Kp, Vtp, Mp, Ap);

    gemm_f16<0><<<gproj, 256, gemm_smem>>>(Ap, wo, b_o, out, NROWS, D_, D_);
}